// round 8
// baseline (speedup 1.0000x reference)
#include <cuda_runtime.h>
#include <cuda_bf16.h>
#include <math.h>
#include <stdint.h>

#define K_DIM 256
#define H_DIM 256
#define OUT_DIM 512
#define G_DIM 256
#define TILE_M 128
#define NTH 512
#define CHUNK_BYTES 16384      // one k32 chunk: [hi 8KB][lo 8KB], 256 n-rows x 32B
#define ASTR 288               // A row stride (bytes) per limb buffer

// ---- smem layout (bytes) ----
#define MBAR 0
#define A_HI 1024
#define A_LO (A_HI + 36864)          // 37888
#define WB   (A_LO + 36864)          // 74752 (128B aligned)
#define PART (WB + 2 * CHUNK_BYTES)  // 107520: 128 rows x 4 warps x float2
#define STAT (PART + 4096)           // 111616: 128 x float2 (mu, rstd)
#define SBID (STAT + 1024)           // 112640: 128 x int
#define SXS  (SBID + 512)            // 113152: 128 x float (row act scales)
#define SMEM_TOTAL (SXS + 512)       // 113664

// ---------------- global scratch ----------------
__device__ float d_Wc[OUT_DIM * K_DIM];
__device__ float d_GAMMA[G_DIM * H_DIM];
__device__ float d_BETA[G_DIM * H_DIM];
__device__ float d_SWS[2048];    // per-row weight scales: which*512 + r
// int8 weight images: per 256-row part: 8 chunks x [hi 8KB | lo 8KB]
// within a chunk: n-row major, 32B/row, k interleaved: pos = ((k&15)>>2)*8 + ((k>>4)&1)*4 + (k&3)
__device__ __align__(128) uint8_t d_W1i[131072];
__device__ __align__(128) uint8_t d_W2i[131072];
__device__ __align__(128) uint8_t d_W3i[262144];

// ---------------- asm helpers ----------------
__device__ __forceinline__ uint32_t smem_u32(const void* p) {
    uint32_t a;
    asm("{ .reg .u64 t; cvta.to.shared.u64 t, %1; cvt.u32.u64 %0, t; }" : "=r"(a) : "l"(p));
    return a;
}
__device__ __forceinline__ void mma_s8(int* c, const uint32_t* a, uint32_t b0, uint32_t b1) {
    asm volatile("mma.sync.aligned.m16n8k32.row.col.s32.s8.s8.s32 "
                 "{%0,%1,%2,%3}, {%4,%5,%6,%7}, {%8,%9}, {%0,%1,%2,%3};"
                 : "+r"(c[0]), "+r"(c[1]), "+r"(c[2]), "+r"(c[3])
                 : "r"(a[0]), "r"(a[1]), "r"(a[2]), "r"(a[3]), "r"(b0), "r"(b1));
}
#define MBAR_INIT(mb, c) asm volatile("mbarrier.init.shared.b64 [%0], %1;" :: "r"(mb), "r"(c) : "memory")
__device__ __forceinline__ void mbar_wait(uint32_t mb, uint32_t parity) {
    asm volatile(
        "{\n\t.reg .pred P1;\n\tW_%=:\n\t"
        "mbarrier.try_wait.parity.acquire.cta.shared::cta.b64 P1, [%0], %1, 0x989680;\n\t"
        "@P1 bra.uni D_%=;\n\tbra.uni W_%=;\n\tD_%=:\n\t}"
        :: "r"(mb), "r"(parity) : "memory");
}
__device__ __forceinline__ void issue_copy(uint32_t sb, int buf, const uint8_t* src, int tid) {
    if (tid == 0) {
        uint32_t mb = sb + MBAR + buf * 8;
        asm volatile("mbarrier.arrive.expect_tx.shared.b64 _, [%0], %1;"
                     :: "r"(mb), "r"(CHUNK_BYTES) : "memory");
        asm volatile("cp.async.bulk.shared::cta.global.mbarrier::complete_tx::bytes "
                     "[%0], [%1], %2, [%3];"
                     :: "r"(sb + WB + buf * CHUNK_BYTES), "l"(src), "r"(CHUNK_BYTES), "r"(mb)
                     : "memory");
    }
}

// quantize y (|y| <= 8000/inv) to q = 64*qh + ql
__device__ __forceinline__ void quant(float y, float inv, int& qh, int& ql) {
    int q = __float2int_rn(y * inv);
    qh = __float2int_rn((float)q * 0.015625f);
    ql = q - (qh << 6);
}
__device__ __forceinline__ int kpos(int k) {  // interleaved byte position within 32B chunk row
    return ((k & 15) >> 2) * 8 + ((k >> 4) & 1) * 4 + (k & 3);
}

// ---------------------------------------------------------------------------
// prep: weight norm -> per-row 13-bit quant -> int8 limb image + row scale
// ---------------------------------------------------------------------------
__global__ void wn_kernel(const float* __restrict__ v, const float* __restrict__ g, int which) {
    int r = blockIdx.x, t = threadIdx.x;
    float x = v[r * K_DIM + t];
    float ss = x * x, ax = fabsf(x);
#pragma unroll
    for (int o = 16; o; o >>= 1) {
        ss += __shfl_xor_sync(0xffffffffu, ss, o);
        ax = fmaxf(ax, __shfl_xor_sync(0xffffffffu, ax, o));
    }
    __shared__ float red[8], redm[8];
    __shared__ float s_scale, s_rmax;
    if ((t & 31) == 0) { red[t >> 5] = ss; redm[t >> 5] = ax; }
    __syncthreads();
    if (t == 0) {
        float tot = 0.f, mx = 0.f;
#pragma unroll
        for (int i = 0; i < 8; i++) { tot += red[i]; mx = fmaxf(mx, redm[i]); }
        float sc = g[r] / sqrtf(tot);
        s_scale = sc;
        s_rmax = mx * fabsf(sc);
        if (which != 0) d_SWS[which * 512 + r] = s_rmax * 1.25e-4f;  // rmax/8000
    }
    __syncthreads();
    float wv = x * s_scale;
    if (which == 0) { d_Wc[r * K_DIM + t] = wv; return; }
    uint8_t* img = (which == 1) ? d_W1i : (which == 2) ? d_W2i : d_W3i;
    int p = r >> 8, n = r & 255;
    img += (size_t)p * 131072;
    float inv = (s_rmax > 0.f) ? 8000.f / s_rmax : 0.f;
    int qh, ql;
    quant(wv, inv, qh, ql);
    int ck = t >> 5, kk = t & 31;
    size_t off = (size_t)ck * CHUNK_BYTES + n * 32 + kpos(kk);
    img[off] = (uint8_t)(qh & 0xff);
    img[off + 8192] = (uint8_t)(ql & 0xff);
}

__global__ void film_kernel(const float* __restrict__ cond, const float* __restrict__ b_cond) {
    __shared__ float cs[K_DIM];
    int g = blockIdx.x, t = threadIdx.x;
    cs[t] = cond[g * K_DIM + t];
    __syncthreads();
    const float* w0 = d_Wc + (size_t)t * K_DIM;
    const float* w1 = d_Wc + (size_t)(t + 256) * K_DIM;
    float a0 = 0.f, a1 = 0.f;
#pragma unroll 8
    for (int k = 0; k < K_DIM; k++) {
        float c = cs[k];
        a0 = fmaf(c, w0[k], a0);
        a1 = fmaf(c, w1[k], a1);
    }
    d_GAMMA[g * H_DIM + t] = a0 + b_cond[t] + 1.0f;
    d_BETA[g * H_DIM + t]  = a1 + b_cond[t + 256];
}

// ---------------------------------------------------------------------------
// one k32 chunk: 3 IMMA terms per 16x8 subtile; fold into fp32 acc (raw units)
// ---------------------------------------------------------------------------
__device__ __forceinline__ void compute_chunk(char* smem, int buf, int ck,
                                              float (&acc)[2][8][4],
                                              int m0, int n0, int lane) {
    const int g = lane >> 2, tg = lane & 3;
    const char* wb = smem + WB + buf * CHUNK_BYTES;
    uint32_t ah[2][4], al[2][4];
#pragma unroll
    for (int mi = 0; mi < 2; mi++) {
        const char* ph = smem + A_HI + (m0 + mi * 16 + g) * ASTR + ck * 32 + tg * 8;
        uint2 u0 = *reinterpret_cast<const uint2*>(ph);
        uint2 u1 = *reinterpret_cast<const uint2*>(ph + 8 * ASTR);
        ah[mi][0] = u0.x; ah[mi][2] = u0.y; ah[mi][1] = u1.x; ah[mi][3] = u1.y;
        const char* pl = smem + A_LO + (m0 + mi * 16 + g) * ASTR + ck * 32 + tg * 8;
        uint2 v0 = *reinterpret_cast<const uint2*>(pl);
        uint2 v1 = *reinterpret_cast<const uint2*>(pl + 8 * ASTR);
        al[mi][0] = v0.x; al[mi][2] = v0.y; al[mi][1] = v1.x; al[mi][3] = v1.y;
    }
#pragma unroll
    for (int j = 0; j < 8; j++) {
        const char* q = wb + (n0 + j * 8 + g) * 32 + tg * 8;
        uint2 bh = *reinterpret_cast<const uint2*>(q);
        uint2 bl = *reinterpret_cast<const uint2*>(q + 8192);
#pragma unroll
        for (int mi = 0; mi < 2; mi++) {
            int S1[4] = {0, 0, 0, 0}, S2[4] = {0, 0, 0, 0};
            mma_s8(S1, ah[mi], bh.x, bh.y);
            mma_s8(S2, ah[mi], bl.x, bl.y);
            mma_s8(S2, al[mi], bh.x, bh.y);
#pragma unroll
            for (int p = 0; p < 4; p++) {
                acc[mi][j][p] = fmaf((float)S1[p], 4096.f, acc[mi][j][p]);
                acc[mi][j][p] = fmaf((float)S2[p], 64.f,   acc[mi][j][p]);
            }
        }
    }
}

// full GEMM over K=256 (8 chunks), double-buffered bulk copies
__device__ __forceinline__ void run_gemm(char* smem, uint32_t sb,
                                         const uint8_t* Wcur, const uint8_t* Wnext,
                                         float (&acc)[2][8][4],
                                         int m0, int n0, int lane, int tid, int (&wph)[2]) {
#pragma unroll
    for (int i = 0; i < 2; i++)
#pragma unroll
        for (int j = 0; j < 8; j++)
#pragma unroll
            for (int p = 0; p < 4; p++) acc[i][j][p] = 0.f;

    __syncthreads();  // order prior A writes before compute
#pragma unroll 1
    for (int ck = 0; ck < 8; ck++) {
        int b = ck & 1;
        mbar_wait(sb + MBAR + b * 8, wph[b] & 1);
        wph[b] ^= 1;
        compute_chunk(smem, b, ck, acc, m0, n0, lane);
        __syncthreads();  // all warps done with buf b before refill
        if (ck < 6)       issue_copy(sb, b, Wcur + (size_t)(ck + 2) * CHUNK_BYTES, tid);
        else if (Wnext)   issue_copy(sb, b, Wnext + (size_t)(ck - 6) * CHUNK_BYTES, tid);
    }
}

// quantize pair (c even, c&3 in {0,2}) and store int8 limbs to A buffers
__device__ __forceinline__ void pack_pair(char* smem, int r, int c, float y0, float y1, float inv) {
    int h0, l0, h1, l1;
    quant(y0, inv, h0, l0);
    quant(y1, inv, h1, l1);
    uint32_t off = r * ASTR + (c >> 5) * 32 + kpos(c & 31);
    *reinterpret_cast<uint16_t*>(smem + A_HI + off) = (uint16_t)((h0 & 0xff) | ((h1 & 0xff) << 8));
    *reinterpret_cast<uint16_t*>(smem + A_LO + off) = (uint16_t)((l0 & 0xff) | ((l1 & 0xff) << 8));
}

// cross-warp per-row max: local -> quad shfl -> PART; caller syncs then reads
__device__ __forceinline__ void rowmax_publish(char* smem, float m, int r, int warp_n, int lq) {
    m = fmaxf(m, __shfl_xor_sync(0xffffffffu, m, 1));
    m = fmaxf(m, __shfl_xor_sync(0xffffffffu, m, 2));
    if (lq == 0) *reinterpret_cast<float*>(smem + PART + (r * 4 + warp_n) * 4) = m;
}
__device__ __forceinline__ float rowmax_read(char* smem, int r) {
    float m = 0.f;
#pragma unroll
    for (int q = 0; q < 4; q++)
        m = fmaxf(m, *reinterpret_cast<float*>(smem + PART + (r * 4 + q) * 4));
    return m;
}

// ---------------------------------------------------------------------------
__global__ void __launch_bounds__(NTH, 1)
fused_mma(const float* __restrict__ x,
          const int* __restrict__ bids,
          const float* __restrict__ b2,
          const float* __restrict__ b3,
          float* __restrict__ out, int N) {
    extern __shared__ __align__(128) char smem[];
    const uint32_t sb = smem_u32(smem);
    const int tid = threadIdx.x;
    const int lane = tid & 31, w = tid >> 5;
    const int warp_m = w >> 2, warp_n = w & 3;
    const int m0 = warp_m * 32, n0 = warp_n * 64;
    const int lgrp = lane >> 2, lq = lane & 3;
    const int row0 = blockIdx.x * TILE_M;

    if (tid == 0) {
        MBAR_INIT(sb + MBAR + 0, 1);
        MBAR_INIT(sb + MBAR + 8, 1);
    }
    __syncthreads();
    issue_copy(sb, 0, d_W1i, tid);
    issue_copy(sb, 1, d_W1i + CHUNK_BYTES, tid);

    // ---- load + quantize X tile: thread t -> row t>>2, k range (t&3)*64..+63 ----
    {
        const int row = tid >> 2, kb = (tid & 3) * 64;
        const int grow = row0 + row;
        float f[64];
        float am = 0.f;
#pragma unroll
        for (int i = 0; i < 16; i++) {
            float4 v = (grow < N)
                ? reinterpret_cast<const float4*>(x)[(size_t)grow * 64 + (kb >> 2) + i]
                : make_float4(0.f, 0.f, 0.f, 0.f);
            f[i * 4 + 0] = v.x; f[i * 4 + 1] = v.y; f[i * 4 + 2] = v.z; f[i * 4 + 3] = v.w;
            am = fmaxf(am, fmaxf(fmaxf(fabsf(v.x), fabsf(v.y)), fmaxf(fabsf(v.z), fabsf(v.w))));
        }
        am = fmaxf(am, __shfl_xor_sync(0xffffffffu, am, 1));
        am = fmaxf(am, __shfl_xor_sync(0xffffffffu, am, 2));
        float inv = (am > 0.f) ? 8000.f / am : 0.f;
        if ((tid & 3) == 0) *reinterpret_cast<float*>(smem + SXS + row * 4) = am * 1.25e-4f;
#pragma unroll
        for (int cc = 0; cc < 2; cc++) {
            uint32_t wh[8], wl[8];
#pragma unroll
            for (int wd = 0; wd < 8; wd++) {
                int kk0 = (wd >> 1) * 4 + (wd & 1) * 16;
                uint32_t hw = 0, lw = 0;
#pragma unroll
                for (int b = 0; b < 4; b++) {
                    int qh, ql;
                    quant(f[cc * 32 + kk0 + b], inv, qh, ql);
                    hw |= (uint32_t)(qh & 0xff) << (8 * b);
                    lw |= (uint32_t)(ql & 0xff) << (8 * b);
                }
                wh[wd] = hw; wl[wd] = lw;
            }
            char* dst = smem + A_HI + row * ASTR + ((tid & 3) * 2 + cc) * 32;
            *reinterpret_cast<uint4*>(dst) = make_uint4(wh[0], wh[1], wh[2], wh[3]);
            *reinterpret_cast<uint4*>(dst + 16) = make_uint4(wh[4], wh[5], wh[6], wh[7]);
            char* dsl = smem + A_LO + row * ASTR + ((tid & 3) * 2 + cc) * 32;
            *reinterpret_cast<uint4*>(dsl) = make_uint4(wl[0], wl[1], wl[2], wl[3]);
            *reinterpret_cast<uint4*>(dsl + 16) = make_uint4(wl[4], wl[5], wl[6], wl[7]);
        }
    }

    float acc[2][8][4];
    int wph[2] = {0, 0};
    float sxr[4];  // per-(mi,half) activation row scales for current A

    // ================= GEMM1 + layernorm/FiLM/relu =================
    run_gemm(smem, sb, d_W1i, d_W2i, acc, m0, n0, lane, tid, wph);
    {
        // de-scale: v = acc * sx_row * sw1_col
        float2 swj[8];
#pragma unroll
        for (int j = 0; j < 8; j++)
            swj[j] = *reinterpret_cast<const float2*>(d_SWS + 512 + n0 + j * 8 + lq * 2);
#pragma unroll
        for (int mi = 0; mi < 2; mi++)
#pragma unroll
            for (int half = 0; half < 2; half++) {
                int r = m0 + mi * 16 + half * 8 + lgrp;
                float sx = *reinterpret_cast<float*>(smem + SXS + r * 4);
#pragma unroll
                for (int j = 0; j < 8; j++) {
                    acc[mi][j][half * 2 + 0] *= sx * swj[j].x;
                    acc[mi][j][half * 2 + 1] *= sx * swj[j].y;
                }
            }
        // ln stats
#pragma unroll
        for (int mi = 0; mi < 2; mi++)
#pragma unroll
            for (int half = 0; half < 2; half++) {
                float s = 0.f, ss = 0.f;
#pragma unroll
                for (int j = 0; j < 8; j++) {
                    float v0 = acc[mi][j][half * 2 + 0];
                    float v1 = acc[mi][j][half * 2 + 1];
                    s += v0 + v1;
                    ss = fmaf(v0, v0, fmaf(v1, v1, ss));
                }
                s  += __shfl_xor_sync(0xffffffffu, s, 1);
                s  += __shfl_xor_sync(0xffffffffu, s, 2);
                ss += __shfl_xor_sync(0xffffffffu, ss, 1);
                ss += __shfl_xor_sync(0xffffffffu, ss, 2);
                if (lq == 0) {
                    int r = m0 + mi * 16 + half * 8 + lgrp;
                    *reinterpret_cast<float2*>(smem + PART + (r * 4 + warp_n) * 8) =
                        make_float2(s, ss);
                }
            }
        __syncthreads();
        if (tid < 128) {
            float s = 0.f, ss = 0.f;
#pragma unroll
            for (int q = 0; q < 4; q++) {
                float2 p = *reinterpret_cast<float2*>(smem + PART + (tid * 4 + q) * 8);
                s += p.x; ss += p.y;
            }
            float mu = s * (1.f / 256.f);
            float var = ss * (1.f / 256.f) - mu * mu;
            float rstd = rsqrtf(var + 1e-5f);
            *reinterpret_cast<float2*>(smem + STAT + tid * 8) = make_float2(mu, rstd);
            int row = row0 + tid;
            *reinterpret_cast<int*>(smem + SBID + tid * 4) = (row < N) ? bids[row] : 0;
        }
        __syncthreads();
        // y = relu(gamma*(v-mu)*rstd + beta)
#pragma unroll
        for (int mi = 0; mi < 2; mi++)
#pragma unroll
            for (int half = 0; half < 2; half++) {
                int r = m0 + mi * 16 + half * 8 + lgrp;
                float2 st = *reinterpret_cast<float2*>(smem + STAT + r * 8);
                int bid = *reinterpret_cast<int*>(smem + SBID + r * 4);
                const float* gp = d_GAMMA + (size_t)bid * H_DIM;
                const float* bp = d_BETA  + (size_t)bid * H_DIM;
                float mx = 0.f;
#pragma unroll
                for (int j = 0; j < 8; j++) {
                    int c = n0 + j * 8 + lq * 2;
                    float2 g2 = *reinterpret_cast<const float2*>(gp + c);
                    float2 be = *reinterpret_cast<const float2*>(bp + c);
                    float y0 = fmaxf(fmaf((acc[mi][j][half * 2 + 0] - st.x) * st.y, g2.x, be.x), 0.f);
                    float y1 = fmaxf(fmaf((acc[mi][j][half * 2 + 1] - st.x) * st.y, g2.y, be.y), 0.f);
                    acc[mi][j][half * 2 + 0] = y0;
                    acc[mi][j][half * 2 + 1] = y1;
                    mx = fmaxf(mx, fmaxf(y0, y1));
                }
                rowmax_publish(smem, mx, r, warp_n, lq);
            }
        __syncthreads();
#pragma unroll
        for (int mi = 0; mi < 2; mi++)
#pragma unroll
            for (int half = 0; half < 2; half++) {
                int r = m0 + mi * 16 + half * 8 + lgrp;
                float rm = rowmax_read(smem, r);
                sxr[mi * 2 + half] = rm * 1.25e-4f;
                float inv = (rm > 0.f) ? 8000.f / rm : 0.f;
#pragma unroll
                for (int j = 0; j < 8; j++) {
                    int c = n0 + j * 8 + lq * 2;
                    pack_pair(smem, r, c, acc[mi][j][half * 2 + 0], acc[mi][j][half * 2 + 1], inv);
                }
            }
    }

    // ================= GEMM2 + relu + b2 =================
    run_gemm(smem, sb, d_W2i, d_W3i, acc, m0, n0, lane, tid, wph);
    {
        float2 swj[8];
#pragma unroll
        for (int j = 0; j < 8; j++)
            swj[j] = *reinterpret_cast<const float2*>(d_SWS + 1024 + n0 + j * 8 + lq * 2);
#pragma unroll
        for (int mi = 0; mi < 2; mi++)
#pragma unroll
            for (int half = 0; half < 2; half++) {
                int r = m0 + mi * 16 + half * 8 + lgrp;
                float sx = sxr[mi * 2 + half];
                float mx = 0.f;
#pragma unroll
                for (int j = 0; j < 8; j++) {
                    int c = n0 + j * 8 + lq * 2;
                    float2 bb = *reinterpret_cast<const float2*>(b2 + c);
                    float y0 = fmaxf(fmaf(acc[mi][j][half * 2 + 0], sx * swj[j].x, bb.x), 0.f);
                    float y1 = fmaxf(fmaf(acc[mi][j][half * 2 + 1], sx * swj[j].y, bb.y), 0.f);
                    acc[mi][j][half * 2 + 0] = y0;
                    acc[mi][j][half * 2 + 1] = y1;
                    mx = fmaxf(mx, fmaxf(y0, y1));
                }
                rowmax_publish(smem, mx, r, warp_n, lq);
            }
        __syncthreads();
#pragma unroll
        for (int mi = 0; mi < 2; mi++)
#pragma unroll
            for (int half = 0; half < 2; half++) {
                int r = m0 + mi * 16 + half * 8 + lgrp;
                float rm = rowmax_read(smem, r);
                sxr[mi * 2 + half] = rm * 1.25e-4f;
                float inv = (rm > 0.f) ? 8000.f / rm : 0.f;
#pragma unroll
                for (int j = 0; j < 8; j++) {
                    int c = n0 + j * 8 + lq * 2;
                    pack_pair(smem, r, c, acc[mi][j][half * 2 + 0], acc[mi][j][half * 2 + 1], inv);
                }
            }
    }

    // ================= GEMM3 (two 256-col halves) + b3 -> out =================
#pragma unroll 1
    for (int hf = 0; hf < 2; hf++) {
        const uint8_t* Wnext = (hf == 0) ? d_W3i + 131072 : nullptr;
        run_gemm(smem, sb, d_W3i + (size_t)hf * 131072, Wnext, acc, m0, n0, lane, tid, wph);
        float2 swj[8];
#pragma unroll
        for (int j = 0; j < 8; j++)
            swj[j] = *reinterpret_cast<const float2*>(d_SWS + 1536 + hf * 256 + n0 + j * 8 + lq * 2);
#pragma unroll
        for (int mi = 0; mi < 2; mi++)
#pragma unroll
            for (int half = 0; half < 2; half++) {
                int r = m0 + mi * 16 + half * 8 + lgrp;
                int row = row0 + r;
                float sx = sxr[mi * 2 + half];
                if (row < N) {
                    float* op = out + (size_t)row * OUT_DIM + hf * 256;
#pragma unroll
                    for (int j = 0; j < 8; j++) {
                        int c = n0 + j * 8 + lq * 2;
                        float2 bb = *reinterpret_cast<const float2*>(b3 + hf * 256 + c);
                        float2 o2;
                        o2.x = fmaf(acc[mi][j][half * 2 + 0], sx * swj[j].x, bb.x);
                        o2.y = fmaf(acc[mi][j][half * 2 + 1], sx * swj[j].y, bb.y);
                        *reinterpret_cast<float2*>(op + c) = o2;
                    }
                }
            }
    }
}

// ---------------------------------------------------------------------------
extern "C" void kernel_launch(void* const* d_in, const int* in_sizes, int n_in,
                              void* d_out, int out_size) {
    const float* x         = (const float*)d_in[0];
    const float* cond      = (const float*)d_in[1];
    const int*   batch_ids = (const int*)  d_in[2];
    const float* v_cond    = (const float*)d_in[3];
    const float* g_cond    = (const float*)d_in[4];
    const float* b_cond    = (const float*)d_in[5];
    const float* v1        = (const float*)d_in[6];
    const float* g1        = (const float*)d_in[7];
    const float* v2        = (const float*)d_in[8];
    const float* g2        = (const float*)d_in[9];
    const float* b2        = (const float*)d_in[10];
    const float* v3        = (const float*)d_in[11];
    const float* g3        = (const float*)d_in[12];
    const float* b3        = (const float*)d_in[13];
    float* out = (float*)d_out;

    int N = in_sizes[0] / K_DIM;

    wn_kernel<<<OUT_DIM, 256>>>(v_cond, g_cond, 0);
    wn_kernel<<<H_DIM,   256>>>(v1, g1, 1);
    wn_kernel<<<H_DIM,   256>>>(v2, g2, 2);
    wn_kernel<<<OUT_DIM, 256>>>(v3, g3, 3);
    film_kernel<<<G_DIM, 256>>>(cond, b_cond);

    cudaFuncSetAttribute(fused_mma, cudaFuncAttributeMaxDynamicSharedMemorySize, SMEM_TOTAL);
    int grid = (N + TILE_M - 1) / TILE_M;
    fused_mma<<<grid, NTH, SMEM_TOTAL>>>(x, batch_ids, b2, b3, out, N);
}

// round 9
// speedup vs baseline: 2.9829x; 2.9829x over previous
#include <cuda_runtime.h>
#include <cuda_fp16.h>
#include <math.h>
#include <stdint.h>

#define K_DIM 256
#define H_DIM 256
#define OUT_DIM 512
#define G_DIM 256
#define TILE_M 128
#define NTH 512
#define CHUNK_BYTES 16384     // one k32 chunk: 256 n-rows x 64B (single fp16 limb)

// ---- smem layout (bytes) ----
#define ASTR_B 528            // 264 fp16 per A row
#define MBAR 0                // 2 mbarriers
#define A_HI 1024
#define A_LO (A_HI + 67584)   // 68608
#define WB   (A_LO + 67584)   // 136192 (128B aligned)
#define PART (WB + 2 * CHUNK_BYTES)  // 168960: 128 rows x 4 warps x float2
#define STAT (PART + 4096)    // 173056: 128 x float2
#define SBID (STAT + 1024)    // 174080: 128 x int
#define SMEM_TOTAL 174592

// ---------------- global scratch ----------------
__device__ float d_Wc[OUT_DIM * K_DIM];
__device__ float d_GAMMA[G_DIM * H_DIM];
__device__ float d_BETA[G_DIM * H_DIM];
// fp16 weight images: per 256-row part: 8 chunks x 16KB, quad-swizzled rows
__device__ __align__(128) uint8_t d_W1i[131072];
__device__ __align__(128) uint8_t d_W2i[131072];
__device__ __align__(128) uint8_t d_W3i[262144];

// ---------------- asm helpers ----------------
__device__ __forceinline__ uint32_t smem_u32(const void* p) {
    uint32_t a;
    asm("{ .reg .u64 t; cvta.to.shared.u64 t, %1; cvt.u32.u64 %0, t; }" : "=r"(a) : "l"(p));
    return a;
}
__device__ __forceinline__ void ldsm4(uint32_t (&r)[4], uint32_t a) {
    asm volatile("ldmatrix.sync.aligned.m8n8.x4.shared.b16 {%0,%1,%2,%3}, [%4];"
                 : "=r"(r[0]), "=r"(r[1]), "=r"(r[2]), "=r"(r[3]) : "r"(a));
}
__device__ __forceinline__ void mma16816(float* c, const uint32_t* a, uint32_t b0, uint32_t b1) {
    asm volatile("mma.sync.aligned.m16n8k16.row.col.f32.f16.f16.f32 "
                 "{%0,%1,%2,%3}, {%4,%5,%6,%7}, {%8,%9}, {%0,%1,%2,%3};"
                 : "+f"(c[0]), "+f"(c[1]), "+f"(c[2]), "+f"(c[3])
                 : "r"(a[0]), "r"(a[1]), "r"(a[2]), "r"(a[3]), "r"(b0), "r"(b1));
}
#define MBAR_INIT(mb, c) asm volatile("mbarrier.init.shared.b64 [%0], %1;" :: "r"(mb), "r"(c) : "memory")
__device__ __forceinline__ void mbar_wait(uint32_t mb, uint32_t parity) {
    asm volatile(
        "{\n\t.reg .pred P1;\n\tW_%=:\n\t"
        "mbarrier.try_wait.parity.acquire.cta.shared::cta.b64 P1, [%0], %1, 0x989680;\n\t"
        "@P1 bra.uni D_%=;\n\tbra.uni W_%=;\n\tD_%=:\n\t}"
        :: "r"(mb), "r"(parity) : "memory");
}
// one 16KB bulk copy of a weight chunk into buf (tid 0 only)
__device__ __forceinline__ void issue_copy(uint32_t sb, int buf, const uint8_t* src, int tid) {
    if (tid == 0) {
        uint32_t mb = sb + MBAR + buf * 8;
        asm volatile("mbarrier.arrive.expect_tx.shared.b64 _, [%0], %1;"
                     :: "r"(mb), "r"(CHUNK_BYTES) : "memory");
        asm volatile("cp.async.bulk.shared::cta.global.mbarrier::complete_tx::bytes "
                     "[%0], [%1], %2, [%3];"
                     :: "r"(sb + WB + buf * CHUNK_BYTES), "l"(src), "r"(CHUNK_BYTES), "r"(mb)
                     : "memory");
    }
}

// ---------------------------------------------------------------------------
// prep: weight norm -> single fp16 -> swizzled chunk image
// ---------------------------------------------------------------------------
__global__ void wn_kernel(const float* __restrict__ v, const float* __restrict__ g, int which) {
    int r = blockIdx.x, t = threadIdx.x;
    float x = v[r * K_DIM + t];
    float ss = x * x;
#pragma unroll
    for (int o = 16; o; o >>= 1) ss += __shfl_xor_sync(0xffffffffu, ss, o);
    __shared__ float red[8];
    __shared__ float s_scale;
    if ((t & 31) == 0) red[t >> 5] = ss;
    __syncthreads();
    if (t == 0) {
        float tot = 0.f;
#pragma unroll
        for (int i = 0; i < 8; i++) tot += red[i];
        s_scale = g[r] / sqrtf(tot);
    }
    __syncthreads();
    float wv = x * s_scale;
    if (which == 0) { d_Wc[r * K_DIM + t] = wv; return; }
    uint8_t* img = (which == 1) ? d_W1i : (which == 2) ? d_W2i : d_W3i;
    int p = r >> 8, n = r & 255;
    img += (size_t)p * 131072;
    int ck = t >> 5, kk = t & 31, q = kk >> 3, e = kk & 7;
    int qs = (q + (n >> 1)) & 3;
    size_t off = (size_t)ck * CHUNK_BYTES + n * 64 + qs * 16 + e * 2;
    *reinterpret_cast<__half*>(img + off) = __float2half(wv);
}

__global__ void film_kernel(const float* __restrict__ cond, const float* __restrict__ b_cond) {
    __shared__ float cs[K_DIM];
    int g = blockIdx.x, t = threadIdx.x;
    cs[t] = cond[g * K_DIM + t];
    __syncthreads();
    const float* w0 = d_Wc + (size_t)t * K_DIM;
    const float* w1 = d_Wc + (size_t)(t + 256) * K_DIM;
    float a0 = 0.f, a1 = 0.f;
#pragma unroll 8
    for (int k = 0; k < K_DIM; k++) {
        float c = cs[k];
        a0 = fmaf(c, w0[k], a0);
        a1 = fmaf(c, w1[k], a1);
    }
    d_GAMMA[g * H_DIM + t] = a0 + b_cond[t] + 1.0f;
    d_BETA[g * H_DIM + t]  = a1 + b_cond[t + 256];
}

// ---------------------------------------------------------------------------
// one k32 chunk: A 2-limb fp16 x W single fp16 => 2 MMA terms
// ---------------------------------------------------------------------------
__device__ __forceinline__ void compute_chunk(uint32_t sb, int buf, int ck,
                                              float (&acc)[2][8][4],
                                              int m0, int n0, int lane) {
    const uint32_t arow = m0 + (lane & 15);
    const uint32_t koff = (lane >> 4) * 8;
    const uint32_t wbase = sb + WB + buf * CHUNK_BYTES;
#pragma unroll
    for (int s = 0; s < 32; s += 16) {
        const int kg = ck * 32 + s;
        uint32_t ah0[4], ah1[4], al0[4], al1[4];
        uint32_t aoff = arow * ASTR_B + (kg + koff) * 2;
        ldsm4(ah0, sb + A_HI + aoff);
        ldsm4(ah1, sb + A_HI + aoff + 16 * ASTR_B);
        ldsm4(al0, sb + A_LO + aoff);
        ldsm4(al1, sb + A_LO + aoff + 16 * ASTR_B);

        const uint32_t q = (uint32_t)(s >> 3) + (lane >> 4);
        uint32_t wf[4][4];
#pragma unroll
        for (int g = 0; g < 4; g++) {
            uint32_t nr = n0 + g * 16 + (lane & 15);
            ldsm4(wf[g], wbase + nr * 64 + (((q + (nr >> 1)) & 3) << 4));
        }
#pragma unroll
        for (int g = 0; g < 4; g++) {
            mma16816(acc[0][2 * g + 0], ah0, wf[g][0], wf[g][2]);
            mma16816(acc[0][2 * g + 1], ah0, wf[g][1], wf[g][3]);
            mma16816(acc[1][2 * g + 0], ah1, wf[g][0], wf[g][2]);
            mma16816(acc[1][2 * g + 1], ah1, wf[g][1], wf[g][3]);
            mma16816(acc[0][2 * g + 0], al0, wf[g][0], wf[g][2]);
            mma16816(acc[0][2 * g + 1], al0, wf[g][1], wf[g][3]);
            mma16816(acc[1][2 * g + 0], al1, wf[g][0], wf[g][2]);
            mma16816(acc[1][2 * g + 1], al1, wf[g][1], wf[g][3]);
        }
    }
}

// full GEMM over K=256 (8 chunks), double-buffered bulk copies.
__device__ __forceinline__ void run_gemm(uint32_t sb, const uint8_t* Wcur, const uint8_t* Wnext,
                                         float (&acc)[2][8][4],
                                         int m0, int n0, int lane, int tid, int (&wph)[2]) {
#pragma unroll
    for (int i = 0; i < 2; i++)
#pragma unroll
        for (int j = 0; j < 8; j++)
#pragma unroll
            for (int qq = 0; qq < 4; qq++) acc[i][j][qq] = 0.f;

    __syncthreads();  // order prior A-tile writes before compute
#pragma unroll 1
    for (int ck = 0; ck < 8; ck++) {
        int b = ck & 1;
        mbar_wait(sb + MBAR + b * 8, wph[b] & 1);
        wph[b] ^= 1;
        compute_chunk(sb, b, ck, acc, m0, n0, lane);
        __syncthreads();  // all warps done with buf b before refill
        if (ck < 6)       issue_copy(sb, b, Wcur + (size_t)(ck + 2) * CHUNK_BYTES, tid);
        else if (Wnext)   issue_copy(sb, b, Wnext + (size_t)(ck - 6) * CHUNK_BYTES, tid);
    }
}

// split fp32 pair -> fp16 hi/lo into A buffers at (row, k)
__device__ __forceinline__ void sts_split2(char* smem, int row, int k, float y0, float y1) {
    __half h0 = __float2half_rn(y0);
    __half l0 = __float2half_rn(y0 - __half2float(h0));
    __half h1 = __float2half_rn(y1);
    __half l1 = __float2half_rn(y1 - __half2float(h1));
    uint32_t off = row * ASTR_B + k * 2;
    *reinterpret_cast<__half2*>(smem + A_HI + off) = __halves2half2(h0, h1);
    *reinterpret_cast<__half2*>(smem + A_LO + off) = __halves2half2(l0, l1);
}

// ---------------------------------------------------------------------------
__global__ void __launch_bounds__(NTH, 1)
fused_mma(const float* __restrict__ x,
          const int* __restrict__ bids,
          const float* __restrict__ b2,
          const float* __restrict__ b3,
          float* __restrict__ out, int N) {
    extern __shared__ __align__(128) char smem[];
    const uint32_t sb = smem_u32(smem);
    const int tid = threadIdx.x;
    const int lane = tid & 31, w = tid >> 5;
    const int warp_m = w >> 2, warp_n = w & 3;
    const int m0 = warp_m * 32, n0 = warp_n * 64;
    const int lgrp = lane >> 2, lq = lane & 3;
    const int row0 = blockIdx.x * TILE_M;

    if (tid == 0) {
        MBAR_INIT(sb + MBAR + 0, 1);
        MBAR_INIT(sb + MBAR + 8, 1);
    }
    __syncthreads();
    // kick off W1 chunks 0,1 immediately (overlap with X staging)
    issue_copy(sb, 0, d_W1i, tid);
    issue_copy(sb, 1, d_W1i + CHUNK_BYTES, tid);

    // ---- build A (hi/lo fp16) from x tile [128 x 256] ----
#pragma unroll 4
    for (int i = 0; i < 16; i++) {
        int idx = tid + NTH * i;
        int m = idx >> 6, c4 = idx & 63;
        int row = row0 + m;
        float4 v = (row < N) ? reinterpret_cast<const float4*>(x)[(size_t)row * 64 + c4]
                             : make_float4(0.f, 0.f, 0.f, 0.f);
        sts_split2(smem, m, c4 * 4 + 0, v.x, v.y);
        sts_split2(smem, m, c4 * 4 + 2, v.z, v.w);
    }

    float acc[2][8][4];
    int wph[2] = {0, 0};

    // ================= GEMM1 + layernorm/FiLM/relu =================
    run_gemm(sb, d_W1i, d_W2i, acc, m0, n0, lane, tid, wph);
    {
#pragma unroll
        for (int mi = 0; mi < 2; mi++)
#pragma unroll
            for (int half = 0; half < 2; half++) {
                float s = 0.f, ss = 0.f;
#pragma unroll
                for (int j = 0; j < 8; j++) {
                    float v0 = acc[mi][j][half * 2 + 0];
                    float v1 = acc[mi][j][half * 2 + 1];
                    s += v0 + v1;
                    ss = fmaf(v0, v0, fmaf(v1, v1, ss));
                }
                s  += __shfl_xor_sync(0xffffffffu, s, 1);
                s  += __shfl_xor_sync(0xffffffffu, s, 2);
                ss += __shfl_xor_sync(0xffffffffu, ss, 1);
                ss += __shfl_xor_sync(0xffffffffu, ss, 2);
                if (lq == 0) {
                    int r = m0 + mi * 16 + half * 8 + lgrp;
                    *reinterpret_cast<float2*>(smem + PART + (r * 4 + warp_n) * 8) =
                        make_float2(s, ss);
                }
            }
        __syncthreads();
        if (tid < 128) {
            float s = 0.f, ss = 0.f;
#pragma unroll
            for (int qq = 0; qq < 4; qq++) {
                float2 p = *reinterpret_cast<float2*>(smem + PART + (tid * 4 + qq) * 8);
                s += p.x;
                ss += p.y;
            }
            float mu = s * (1.f / 256.f);
            float var = ss * (1.f / 256.f) - mu * mu;
            float rstd = rsqrtf(var + 1e-5f);
            *reinterpret_cast<float2*>(smem + STAT + tid * 8) = make_float2(mu, rstd);
            int row = row0 + tid;
            *reinterpret_cast<int*>(smem + SBID + tid * 4) = (row < N) ? bids[row] : 0;
        }
        __syncthreads();
#pragma unroll
        for (int mi = 0; mi < 2; mi++)
#pragma unroll
            for (int half = 0; half < 2; half++) {
                int r = m0 + mi * 16 + half * 8 + lgrp;
                float2 st = *reinterpret_cast<float2*>(smem + STAT + r * 8);
                int bid = *reinterpret_cast<int*>(smem + SBID + r * 4);
                const float* gp = d_GAMMA + (size_t)bid * H_DIM;
                const float* bp = d_BETA  + (size_t)bid * H_DIM;
#pragma unroll
                for (int j = 0; j < 8; j++) {
                    int c = n0 + j * 8 + lq * 2;
                    float2 g2 = *reinterpret_cast<const float2*>(gp + c);
                    float2 be = *reinterpret_cast<const float2*>(bp + c);
                    float y0 = fmaxf(fmaf((acc[mi][j][half * 2 + 0] - st.x) * st.y, g2.x, be.x), 0.f);
                    float y1 = fmaxf(fmaf((acc[mi][j][half * 2 + 1] - st.x) * st.y, g2.y, be.y), 0.f);
                    sts_split2(smem, r, c, y0, y1);
                }
            }
    }

    // ================= GEMM2 + relu + b2 =================
    run_gemm(sb, d_W2i, d_W3i, acc, m0, n0, lane, tid, wph);
    {
#pragma unroll
        for (int mi = 0; mi < 2; mi++)
#pragma unroll
            for (int half = 0; half < 2; half++) {
                int r = m0 + mi * 16 + half * 8 + lgrp;
#pragma unroll
                for (int j = 0; j < 8; j++) {
                    int c = n0 + j * 8 + lq * 2;
                    float2 bb = *reinterpret_cast<const float2*>(b2 + c);
                    float y0 = fmaxf(acc[mi][j][half * 2 + 0] + bb.x, 0.f);
                    float y1 = fmaxf(acc[mi][j][half * 2 + 1] + bb.y, 0.f);
                    sts_split2(smem, r, c, y0, y1);
                }
            }
    }

    // ================= GEMM3 (two 256-col halves) + b3 -> out =================
#pragma unroll 1
    for (int hf = 0; hf < 2; hf++) {
        const uint8_t* Wnext = (hf == 0) ? d_W3i + 131072 : nullptr;
        run_gemm(sb, d_W3i + (size_t)hf * 131072, Wnext, acc, m0, n0, lane, tid, wph);
#pragma unroll
        for (int mi = 0; mi < 2; mi++)
#pragma unroll
            for (int half = 0; half < 2; half++) {
                int r = m0 + mi * 16 + half * 8 + lgrp;
                int row = row0 + r;
                if (row < N) {
                    float* op = out + (size_t)row * OUT_DIM + hf * 256;
#pragma unroll
                    for (int j = 0; j < 8; j++) {
                        int c = n0 + j * 8 + lq * 2;
                        float2 bb = *reinterpret_cast<const float2*>(b3 + hf * 256 + c);
                        float2 o2;
                        o2.x = acc[mi][j][half * 2 + 0] + bb.x;
                        o2.y = acc[mi][j][half * 2 + 1] + bb.y;
                        *reinterpret_cast<float2*>(op + c) = o2;
                    }
                }
            }
    }
}

// ---------------------------------------------------------------------------
extern "C" void kernel_launch(void* const* d_in, const int* in_sizes, int n_in,
                              void* d_out, int out_size) {
    const float* x         = (const float*)d_in[0];
    const float* cond      = (const float*)d_in[1];
    const int*   batch_ids = (const int*)  d_in[2];
    const float* v_cond    = (const float*)d_in[3];
    const float* g_cond    = (const float*)d_in[4];
    const float* b_cond    = (const float*)d_in[5];
    const float* v1        = (const float*)d_in[6];
    const float* g1        = (const float*)d_in[7];
    const float* v2        = (const float*)d_in[8];
    const float* g2        = (const float*)d_in[9];
    const float* b2        = (const float*)d_in[10];
    const float* v3        = (const float*)d_in[11];
    const float* g3        = (const float*)d_in[12];
    const float* b3        = (const float*)d_in[13];
    float* out = (float*)d_out;

    int N = in_sizes[0] / K_DIM;

    wn_kernel<<<OUT_DIM, 256>>>(v_cond, g_cond, 0);
    wn_kernel<<<H_DIM,   256>>>(v1, g1, 1);
    wn_kernel<<<H_DIM,   256>>>(v2, g2, 2);
    wn_kernel<<<OUT_DIM, 256>>>(v3, g3, 3);
    film_kernel<<<G_DIM, 256>>>(cond, b_cond);

    cudaFuncSetAttribute(fused_mma, cudaFuncAttributeMaxDynamicSharedMemorySize, SMEM_TOTAL);
    int grid = (N + TILE_M - 1) / TILE_M;
    fused_mma<<<grid, NTH, SMEM_TOTAL>>>(x, batch_ids, b2, b3, out, N);
}

// round 10
// speedup vs baseline: 3.7194x; 1.2469x over previous
#include <cuda_runtime.h>
#include <cuda_fp16.h>
#include <math.h>
#include <stdint.h>

#define K_DIM 256
#define H_DIM 256
#define OUT_DIM 512
#define G_DIM 256
#define TILE_M 128
#define NTH 512
#define CHUNK_BYTES 16384     // one k32 chunk: 256 n-rows x 64B (single fp16)

// ---- smem layout (bytes) ----
#define ASTR_B 528            // 264 fp16 per A row
#define MBAR 0
#define A_HI 1024
#define A_LO (A_HI + 67584)   // 68608
#define WB   (A_LO + 67584)   // 136192 (128B aligned)
#define PART (WB + 2 * CHUNK_BYTES)  // 168960
#define STAT (PART + 4096)    // 173056
#define SBID (STAT + 1024)    // 174080
#define SMEM_TOTAL 174592

// ---------------- global scratch ----------------
__device__ float d_Wc[OUT_DIM * K_DIM];
__device__ float d_GAMMA[G_DIM * H_DIM];
__device__ float d_BETA[G_DIM * H_DIM];
__device__ __align__(128) uint8_t d_W1i[131072];
__device__ __align__(128) uint8_t d_W2i[131072];
__device__ __align__(128) uint8_t d_W3i[262144];

// ---------------- asm helpers ----------------
__device__ __forceinline__ uint32_t smem_u32(const void* p) {
    uint32_t a;
    asm("{ .reg .u64 t; cvta.to.shared.u64 t, %1; cvt.u32.u64 %0, t; }" : "=r"(a) : "l"(p));
    return a;
}
__device__ __forceinline__ void ldsm4(uint32_t (&r)[4], uint32_t a) {
    asm volatile("ldmatrix.sync.aligned.m8n8.x4.shared.b16 {%0,%1,%2,%3}, [%4];"
                 : "=r"(r[0]), "=r"(r[1]), "=r"(r[2]), "=r"(r[3]) : "r"(a));
}
__device__ __forceinline__ void mma16816(float* c, const uint32_t* a, uint32_t b0, uint32_t b1) {
    asm volatile("mma.sync.aligned.m16n8k16.row.col.f32.f16.f16.f32 "
                 "{%0,%1,%2,%3}, {%4,%5,%6,%7}, {%8,%9}, {%0,%1,%2,%3};"
                 : "+f"(c[0]), "+f"(c[1]), "+f"(c[2]), "+f"(c[3])
                 : "r"(a[0]), "r"(a[1]), "r"(a[2]), "r"(a[3]), "r"(b0), "r"(b1));
}
#define MBAR_INIT(mb, c) asm volatile("mbarrier.init.shared.b64 [%0], %1;" :: "r"(mb), "r"(c) : "memory")
__device__ __forceinline__ void mbar_wait(uint32_t mb, uint32_t parity) {
    asm volatile(
        "{\n\t.reg .pred P1;\n\tW_%=:\n\t"
        "mbarrier.try_wait.parity.acquire.cta.shared::cta.b64 P1, [%0], %1, 0x989680;\n\t"
        "@P1 bra.uni D_%=;\n\tbra.uni W_%=;\n\tD_%=:\n\t}"
        :: "r"(mb), "r"(parity) : "memory");
}
__device__ __forceinline__ void issue_copy(uint32_t sb, int buf, const uint8_t* src, int tid) {
    if (tid == 0) {
        uint32_t mb = sb + MBAR + buf * 8;
        asm volatile("mbarrier.arrive.expect_tx.shared.b64 _, [%0], %1;"
                     :: "r"(mb), "r"(CHUNK_BYTES) : "memory");
        asm volatile("cp.async.bulk.shared::cta.global.mbarrier::complete_tx::bytes "
                     "[%0], [%1], %2, [%3];"
                     :: "r"(sb + WB + buf * CHUNK_BYTES), "l"(src), "r"(CHUNK_BYTES), "r"(mb)
                     : "memory");
    }
}

// ---------------------------------------------------------------------------
// prep kernels
// ---------------------------------------------------------------------------
__global__ void wn_kernel(const float* __restrict__ v, const float* __restrict__ g, int which) {
    int r = blockIdx.x, t = threadIdx.x;
    float x = v[r * K_DIM + t];
    float ss = x * x;
#pragma unroll
    for (int o = 16; o; o >>= 1) ss += __shfl_xor_sync(0xffffffffu, ss, o);
    __shared__ float red[8];
    __shared__ float s_scale;
    if ((t & 31) == 0) red[t >> 5] = ss;
    __syncthreads();
    if (t == 0) {
        float tot = 0.f;
#pragma unroll
        for (int i = 0; i < 8; i++) tot += red[i];
        s_scale = g[r] / sqrtf(tot);
    }
    __syncthreads();
    float wv = x * s_scale;
    if (which == 0) { d_Wc[r * K_DIM + t] = wv; return; }
    uint8_t* img = (which == 1) ? d_W1i : (which == 2) ? d_W2i : d_W3i;
    int p = r >> 8, n = r & 255;
    img += (size_t)p * 131072;
    int ck = t >> 5, kk = t & 31, q = kk >> 3, e = kk & 7;
    int qs = (q + (n >> 1)) & 3;
    size_t off = (size_t)ck * CHUNK_BYTES + n * 64 + qs * 16 + e * 2;
    *reinterpret_cast<__half*>(img + off) = __float2half(wv);
}

__global__ void film_kernel(const float* __restrict__ cond, const float* __restrict__ b_cond) {
    __shared__ float cs[K_DIM];
    int g = blockIdx.x, t = threadIdx.x;
    cs[t] = cond[g * K_DIM + t];
    __syncthreads();
    const float* w0 = d_Wc + (size_t)t * K_DIM;
    const float* w1 = d_Wc + (size_t)(t + 256) * K_DIM;
    float a0 = 0.f, a1 = 0.f;
#pragma unroll 8
    for (int k = 0; k < K_DIM; k++) {
        float c = cs[k];
        a0 = fmaf(c, w0[k], a0);
        a1 = fmaf(c, w1[k], a1);
    }
    d_GAMMA[g * H_DIM + t] = a0 + b_cond[t] + 1.0f;
    d_BETA[g * H_DIM + t]  = a1 + b_cond[t + 256];
}

// ---------------------------------------------------------------------------
// one k32 chunk. LO: include A low-limb MMAs (GEMM1 only)
// ---------------------------------------------------------------------------
template <bool LO>
__device__ __forceinline__ void compute_chunk(uint32_t sb, int buf, int ck,
                                              float (&acc)[2][8][4],
                                              int m0, int n0, int lane) {
    const uint32_t arow = m0 + (lane & 15);
    const uint32_t koff = (lane >> 4) * 8;
    const uint32_t wbase = sb + WB + buf * CHUNK_BYTES;
#pragma unroll
    for (int s = 0; s < 32; s += 16) {
        const int kg = ck * 32 + s;
        uint32_t ah0[4], ah1[4], al0[4], al1[4];
        uint32_t aoff = arow * ASTR_B + (kg + koff) * 2;
        ldsm4(ah0, sb + A_HI + aoff);
        ldsm4(ah1, sb + A_HI + aoff + 16 * ASTR_B);
        if (LO) {
            ldsm4(al0, sb + A_LO + aoff);
            ldsm4(al1, sb + A_LO + aoff + 16 * ASTR_B);
        }
        const uint32_t q = (uint32_t)(s >> 3) + (lane >> 4);
        uint32_t wf[4][4];
#pragma unroll
        for (int g = 0; g < 4; g++) {
            uint32_t nr = n0 + g * 16 + (lane & 15);
            ldsm4(wf[g], wbase + nr * 64 + (((q + (nr >> 1)) & 3) << 4));
        }
#pragma unroll
        for (int g = 0; g < 4; g++) {
            mma16816(acc[0][2 * g + 0], ah0, wf[g][0], wf[g][2]);
            mma16816(acc[0][2 * g + 1], ah0, wf[g][1], wf[g][3]);
            mma16816(acc[1][2 * g + 0], ah1, wf[g][0], wf[g][2]);
            mma16816(acc[1][2 * g + 1], ah1, wf[g][1], wf[g][3]);
            if (LO) {
                mma16816(acc[0][2 * g + 0], al0, wf[g][0], wf[g][2]);
                mma16816(acc[0][2 * g + 1], al0, wf[g][1], wf[g][3]);
                mma16816(acc[1][2 * g + 0], al1, wf[g][0], wf[g][2]);
                mma16816(acc[1][2 * g + 1], al1, wf[g][1], wf[g][3]);
            }
        }
    }
}

template <bool LO>
__device__ __forceinline__ void run_gemm(uint32_t sb, const uint8_t* Wcur, const uint8_t* Wnext,
                                         float (&acc)[2][8][4],
                                         int m0, int n0, int lane, int tid, int (&wph)[2]) {
#pragma unroll
    for (int i = 0; i < 2; i++)
#pragma unroll
        for (int j = 0; j < 8; j++)
#pragma unroll
            for (int qq = 0; qq < 4; qq++) acc[i][j][qq] = 0.f;

    __syncthreads();  // order prior A-tile writes before compute
#pragma unroll 1
    for (int ck = 0; ck < 8; ck++) {
        int b = ck & 1;
        mbar_wait(sb + MBAR + b * 8, wph[b] & 1);
        wph[b] ^= 1;
        compute_chunk<LO>(sb, b, ck, acc, m0, n0, lane);
        __syncthreads();  // all warps done with buf b before refill
        if (ck < 6)       issue_copy(sb, b, Wcur + (size_t)(ck + 2) * CHUNK_BYTES, tid);
        else if (Wnext)   issue_copy(sb, b, Wnext + (size_t)(ck - 6) * CHUNK_BYTES, tid);
    }
}

// 2-limb store (GEMM1 input)
__device__ __forceinline__ void sts_split2(char* smem, int row, int k, float y0, float y1) {
    __half h0 = __float2half_rn(y0);
    __half l0 = __float2half_rn(y0 - __half2float(h0));
    __half h1 = __float2half_rn(y1);
    __half l1 = __float2half_rn(y1 - __half2float(h1));
    uint32_t off = row * ASTR_B + k * 2;
    *reinterpret_cast<__half2*>(smem + A_HI + off) = __halves2half2(h0, h1);
    *reinterpret_cast<__half2*>(smem + A_LO + off) = __halves2half2(l0, l1);
}
// single-limb store (GEMM2/3 inputs)
__device__ __forceinline__ void sts_single2(char* smem, int row, int k, float y0, float y1) {
    uint32_t off = row * ASTR_B + k * 2;
    *reinterpret_cast<__half2*>(smem + A_HI + off) =
        __halves2half2(__float2half_rn(y0), __float2half_rn(y1));
}

// ---------------------------------------------------------------------------
__global__ void __launch_bounds__(NTH, 1)
fused_mma(const float* __restrict__ x,
          const int* __restrict__ bids,
          const float* __restrict__ b2,
          const float* __restrict__ b3,
          float* __restrict__ out, int N) {
    extern __shared__ __align__(128) char smem[];
    const uint32_t sb = smem_u32(smem);
    const int tid = threadIdx.x;
    const int lane = tid & 31, w = tid >> 5;
    const int warp_m = w >> 2, warp_n = w & 3;
    const int m0 = warp_m * 32, n0 = warp_n * 64;
    const int lgrp = lane >> 2, lq = lane & 3;
    const int row0 = blockIdx.x * TILE_M;

    if (tid == 0) {
        MBAR_INIT(sb + MBAR + 0, 1);
        MBAR_INIT(sb + MBAR + 8, 1);
    }
    __syncthreads();
    issue_copy(sb, 0, d_W1i, tid);
    issue_copy(sb, 1, d_W1i + CHUNK_BYTES, tid);

    // ---- build A (hi/lo fp16) from x tile [128 x 256] ----
#pragma unroll 4
    for (int i = 0; i < 16; i++) {
        int idx = tid + NTH * i;
        int m = idx >> 6, c4 = idx & 63;
        int row = row0 + m;
        float4 v = (row < N) ? reinterpret_cast<const float4*>(x)[(size_t)row * 64 + c4]
                             : make_float4(0.f, 0.f, 0.f, 0.f);
        sts_split2(smem, m, c4 * 4 + 0, v.x, v.y);
        sts_split2(smem, m, c4 * 4 + 2, v.z, v.w);
    }

    float acc[2][8][4];
    int wph[2] = {0, 0};

    // ================= GEMM1 (2-limb A) + layernorm/FiLM/relu =================
    run_gemm<true>(sb, d_W1i, d_W2i, acc, m0, n0, lane, tid, wph);
    {
#pragma unroll
        for (int mi = 0; mi < 2; mi++)
#pragma unroll
            for (int half = 0; half < 2; half++) {
                float s = 0.f, ss = 0.f;
#pragma unroll
                for (int j = 0; j < 8; j++) {
                    float v0 = acc[mi][j][half * 2 + 0];
                    float v1 = acc[mi][j][half * 2 + 1];
                    s += v0 + v1;
                    ss = fmaf(v0, v0, fmaf(v1, v1, ss));
                }
                s  += __shfl_xor_sync(0xffffffffu, s, 1);
                s  += __shfl_xor_sync(0xffffffffu, s, 2);
                ss += __shfl_xor_sync(0xffffffffu, ss, 1);
                ss += __shfl_xor_sync(0xffffffffu, ss, 2);
                if (lq == 0) {
                    int r = m0 + mi * 16 + half * 8 + lgrp;
                    *reinterpret_cast<float2*>(smem + PART + (r * 4 + warp_n) * 8) =
                        make_float2(s, ss);
                }
            }
        __syncthreads();
        if (tid < 128) {
            float s = 0.f, ss = 0.f;
#pragma unroll
            for (int qq = 0; qq < 4; qq++) {
                float2 p = *reinterpret_cast<float2*>(smem + PART + (tid * 4 + qq) * 8);
                s += p.x;
                ss += p.y;
            }
            float mu = s * (1.f / 256.f);
            float var = ss * (1.f / 256.f) - mu * mu;
            float rstd = rsqrtf(var + 1e-5f);
            *reinterpret_cast<float2*>(smem + STAT + tid * 8) = make_float2(mu, rstd);
            int row = row0 + tid;
            *reinterpret_cast<int*>(smem + SBID + tid * 4) = (row < N) ? bids[row] : 0;
        }
        __syncthreads();
#pragma unroll
        for (int mi = 0; mi < 2; mi++)
#pragma unroll
            for (int half = 0; half < 2; half++) {
                int r = m0 + mi * 16 + half * 8 + lgrp;
                float2 st = *reinterpret_cast<float2*>(smem + STAT + r * 8);
                int bid = *reinterpret_cast<int*>(smem + SBID + r * 4);
                const float* gp = d_GAMMA + (size_t)bid * H_DIM;
                const float* bp = d_BETA  + (size_t)bid * H_DIM;
#pragma unroll
                for (int j = 0; j < 8; j++) {
                    int c = n0 + j * 8 + lq * 2;
                    float2 g2 = *reinterpret_cast<const float2*>(gp + c);
                    float2 be = *reinterpret_cast<const float2*>(bp + c);
                    float y0 = fmaxf(fmaf((acc[mi][j][half * 2 + 0] - st.x) * st.y, g2.x, be.x), 0.f);
                    float y1 = fmaxf(fmaf((acc[mi][j][half * 2 + 1] - st.x) * st.y, g2.y, be.y), 0.f);
                    sts_single2(smem, r, c, y0, y1);
                }
            }
    }

    // ================= GEMM2 (single A) + relu + b2 =================
    run_gemm<false>(sb, d_W2i, d_W3i, acc, m0, n0, lane, tid, wph);
    {
#pragma unroll
        for (int mi = 0; mi < 2; mi++)
#pragma unroll
            for (int half = 0; half < 2; half++) {
                int r = m0 + mi * 16 + half * 8 + lgrp;
#pragma unroll
                for (int j = 0; j < 8; j++) {
                    int c = n0 + j * 8 + lq * 2;
                    float2 bb = *reinterpret_cast<const float2*>(b2 + c);
                    float y0 = fmaxf(acc[mi][j][half * 2 + 0] + bb.x, 0.f);
                    float y1 = fmaxf(acc[mi][j][half * 2 + 1] + bb.y, 0.f);
                    sts_single2(smem, r, c, y0, y1);
                }
            }
    }

    // ================= GEMM3 (single A, two 256-col halves) + b3 -> out =====
#pragma unroll 1
    for (int hf = 0; hf < 2; hf++) {
        const uint8_t* Wnext = (hf == 0) ? d_W3i + 131072 : nullptr;
        run_gemm<false>(sb, d_W3i + (size_t)hf * 131072, Wnext, acc, m0, n0, lane, tid, wph);
#pragma unroll
        for (int mi = 0; mi < 2; mi++)
#pragma unroll
            for (int half = 0; half < 2; half++) {
                int r = m0 + mi * 16 + half * 8 + lgrp;
                int row = row0 + r;
                if (row < N) {
                    float* op = out + (size_t)row * OUT_DIM + hf * 256;
#pragma unroll
                    for (int j = 0; j < 8; j++) {
                        int c = n0 + j * 8 + lq * 2;
                        float2 bb = *reinterpret_cast<const float2*>(b3 + hf * 256 + c);
                        float2 o2;
                        o2.x = acc[mi][j][half * 2 + 0] + bb.x;
                        o2.y = acc[mi][j][half * 2 + 1] + bb.y;
                        *reinterpret_cast<float2*>(op + c) = o2;
                    }
                }
            }
    }
}

// ---------------------------------------------------------------------------
extern "C" void kernel_launch(void* const* d_in, const int* in_sizes, int n_in,
                              void* d_out, int out_size) {
    const float* x         = (const float*)d_in[0];
    const float* cond      = (const float*)d_in[1];
    const int*   batch_ids = (const int*)  d_in[2];
    const float* v_cond    = (const float*)d_in[3];
    const float* g_cond    = (const float*)d_in[4];
    const float* b_cond    = (const float*)d_in[5];
    const float* v1        = (const float*)d_in[6];
    const float* g1        = (const float*)d_in[7];
    const float* v2        = (const float*)d_in[8];
    const float* g2        = (const float*)d_in[9];
    const float* b2        = (const float*)d_in[10];
    const float* v3        = (const float*)d_in[11];
    const float* g3        = (const float*)d_in[12];
    const float* b3        = (const float*)d_in[13];
    float* out = (float*)d_out;

    int N = in_sizes[0] / K_DIM;

    wn_kernel<<<OUT_DIM, 256>>>(v_cond, g_cond, 0);
    wn_kernel<<<H_DIM,   256>>>(v1, g1, 1);
    wn_kernel<<<H_DIM,   256>>>(v2, g2, 2);
    wn_kernel<<<OUT_DIM, 256>>>(v3, g3, 3);
    film_kernel<<<G_DIM, 256>>>(cond, b_cond);

    cudaFuncSetAttribute(fused_mma, cudaFuncAttributeMaxDynamicSharedMemorySize, SMEM_TOTAL);
    int grid = (N + TILE_M - 1) / TILE_M;
    fused_mma<<<grid, NTH, SMEM_TOTAL>>>(x, batch_ids, b2, b3, out, N);
}

// round 11
// speedup vs baseline: 4.3503x; 1.1696x over previous
#include <cuda_runtime.h>
#include <cuda_fp16.h>
#include <math.h>
#include <stdint.h>

#define K_DIM 256
#define H_DIM 256
#define OUT_DIM 512
#define G_DIM 256
#define TILE_M 64
#define NTH 256
#define CHUNK_BYTES 16384     // one k32 chunk: 256 n-rows x 64B (single fp16)

// ---- smem layout (bytes) ----
#define ASTR_B 528            // 264 fp16 per A row
#define MBAR 0
#define A_HI 1024
#define A_LO (A_HI + 33792)   // 34816
#define WB   (A_LO + 33792)   // 68608 (128B aligned)
#define PART (WB + 2 * CHUNK_BYTES)  // 101376: 64 rows x 4 warps x float2
#define STAT (PART + 2048)    // 103424: 64 x float2
#define SBID (STAT + 512)     // 103936: 64 x int
#define SMEM_TOTAL 104192

// ---------------- global scratch ----------------
__device__ float d_Wc[OUT_DIM * K_DIM];
__device__ float d_GAMMA[G_DIM * H_DIM];
__device__ float d_BETA[G_DIM * H_DIM];
__device__ __align__(128) uint8_t d_W1i[131072];
__device__ __align__(128) uint8_t d_W2i[131072];
__device__ __align__(128) uint8_t d_W3i[262144];

// ---------------- asm helpers ----------------
__device__ __forceinline__ uint32_t smem_u32(const void* p) {
    uint32_t a;
    asm("{ .reg .u64 t; cvta.to.shared.u64 t, %1; cvt.u32.u64 %0, t; }" : "=r"(a) : "l"(p));
    return a;
}
__device__ __forceinline__ void ldsm4(uint32_t (&r)[4], uint32_t a) {
    asm volatile("ldmatrix.sync.aligned.m8n8.x4.shared.b16 {%0,%1,%2,%3}, [%4];"
                 : "=r"(r[0]), "=r"(r[1]), "=r"(r[2]), "=r"(r[3]) : "r"(a));
}
__device__ __forceinline__ void mma16816(float* c, const uint32_t* a, uint32_t b0, uint32_t b1) {
    asm volatile("mma.sync.aligned.m16n8k16.row.col.f32.f16.f16.f32 "
                 "{%0,%1,%2,%3}, {%4,%5,%6,%7}, {%8,%9}, {%0,%1,%2,%3};"
                 : "+f"(c[0]), "+f"(c[1]), "+f"(c[2]), "+f"(c[3])
                 : "r"(a[0]), "r"(a[1]), "r"(a[2]), "r"(a[3]), "r"(b0), "r"(b1));
}
#define MBAR_INIT(mb, c) asm volatile("mbarrier.init.shared.b64 [%0], %1;" :: "r"(mb), "r"(c) : "memory")
__device__ __forceinline__ void mbar_wait(uint32_t mb, uint32_t parity) {
    asm volatile(
        "{\n\t.reg .pred P1;\n\tW_%=:\n\t"
        "mbarrier.try_wait.parity.acquire.cta.shared::cta.b64 P1, [%0], %1, 0x989680;\n\t"
        "@P1 bra.uni D_%=;\n\tbra.uni W_%=;\n\tD_%=:\n\t}"
        :: "r"(mb), "r"(parity) : "memory");
}
__device__ __forceinline__ void issue_copy(uint32_t sb, int buf, const uint8_t* src, int tid) {
    if (tid == 0) {
        uint32_t mb = sb + MBAR + buf * 8;
        asm volatile("mbarrier.arrive.expect_tx.shared.b64 _, [%0], %1;"
                     :: "r"(mb), "r"(CHUNK_BYTES) : "memory");
        asm volatile("cp.async.bulk.shared::cta.global.mbarrier::complete_tx::bytes "
                     "[%0], [%1], %2, [%3];"
                     :: "r"(sb + WB + buf * CHUNK_BYTES), "l"(src), "r"(CHUNK_BYTES), "r"(mb)
                     : "memory");
    }
}

// ---------------------------------------------------------------------------
// prep kernels
// ---------------------------------------------------------------------------
__global__ void wn_kernel(const float* __restrict__ v, const float* __restrict__ g, int which) {
    int r = blockIdx.x, t = threadIdx.x;
    float x = v[r * K_DIM + t];
    float ss = x * x;
#pragma unroll
    for (int o = 16; o; o >>= 1) ss += __shfl_xor_sync(0xffffffffu, ss, o);
    __shared__ float red[8];
    __shared__ float s_scale;
    if ((t & 31) == 0) red[t >> 5] = ss;
    __syncthreads();
    if (t == 0) {
        float tot = 0.f;
#pragma unroll
        for (int i = 0; i < 8; i++) tot += red[i];
        s_scale = g[r] / sqrtf(tot);
    }
    __syncthreads();
    float wv = x * s_scale;
    if (which == 0) { d_Wc[r * K_DIM + t] = wv; return; }
    uint8_t* img = (which == 1) ? d_W1i : (which == 2) ? d_W2i : d_W3i;
    int p = r >> 8, n = r & 255;
    img += (size_t)p * 131072;
    int ck = t >> 5, kk = t & 31, q = kk >> 3, e = kk & 7;
    int qs = (q + (n >> 1)) & 3;
    size_t off = (size_t)ck * CHUNK_BYTES + n * 64 + qs * 16 + e * 2;
    *reinterpret_cast<__half*>(img + off) = __float2half(wv);
}

__global__ void film_kernel(const float* __restrict__ cond, const float* __restrict__ b_cond) {
    __shared__ float cs[K_DIM];
    int g = blockIdx.x, t = threadIdx.x;
    cs[t] = cond[g * K_DIM + t];
    __syncthreads();
    const float* w0 = d_Wc + (size_t)t * K_DIM;
    const float* w1 = d_Wc + (size_t)(t + 256) * K_DIM;
    float a0 = 0.f, a1 = 0.f;
#pragma unroll 8
    for (int k = 0; k < K_DIM; k++) {
        float c = cs[k];
        a0 = fmaf(c, w0[k], a0);
        a1 = fmaf(c, w1[k], a1);
    }
    d_GAMMA[g * H_DIM + t] = a0 + b_cond[t] + 1.0f;
    d_BETA[g * H_DIM + t]  = a1 + b_cond[t + 256];
}

// ---------------------------------------------------------------------------
// one k32 chunk. LO: include A low-limb MMAs (GEMM1 only)
// ---------------------------------------------------------------------------
template <bool LO>
__device__ __forceinline__ void compute_chunk(uint32_t sb, int buf, int ck,
                                              float (&acc)[2][8][4],
                                              int m0, int n0, int lane) {
    const uint32_t arow = m0 + (lane & 15);
    const uint32_t koff = (lane >> 4) * 8;
    const uint32_t wbase = sb + WB + buf * CHUNK_BYTES;
#pragma unroll
    for (int s = 0; s < 32; s += 16) {
        const int kg = ck * 32 + s;
        uint32_t ah0[4], ah1[4], al0[4], al1[4];
        uint32_t aoff = arow * ASTR_B + (kg + koff) * 2;
        ldsm4(ah0, sb + A_HI + aoff);
        ldsm4(ah1, sb + A_HI + aoff + 16 * ASTR_B);
        if (LO) {
            ldsm4(al0, sb + A_LO + aoff);
            ldsm4(al1, sb + A_LO + aoff + 16 * ASTR_B);
        }
        const uint32_t q = (uint32_t)(s >> 3) + (lane >> 4);
        uint32_t wf[4][4];
#pragma unroll
        for (int g = 0; g < 4; g++) {
            uint32_t nr = n0 + g * 16 + (lane & 15);
            ldsm4(wf[g], wbase + nr * 64 + (((q + (nr >> 1)) & 3) << 4));
        }
#pragma unroll
        for (int g = 0; g < 4; g++) {
            mma16816(acc[0][2 * g + 0], ah0, wf[g][0], wf[g][2]);
            mma16816(acc[0][2 * g + 1], ah0, wf[g][1], wf[g][3]);
            mma16816(acc[1][2 * g + 0], ah1, wf[g][0], wf[g][2]);
            mma16816(acc[1][2 * g + 1], ah1, wf[g][1], wf[g][3]);
            if (LO) {
                mma16816(acc[0][2 * g + 0], al0, wf[g][0], wf[g][2]);
                mma16816(acc[0][2 * g + 1], al0, wf[g][1], wf[g][3]);
                mma16816(acc[1][2 * g + 0], al1, wf[g][0], wf[g][2]);
                mma16816(acc[1][2 * g + 1], al1, wf[g][1], wf[g][3]);
            }
        }
    }
}

template <bool LO>
__device__ __forceinline__ void run_gemm(uint32_t sb, const uint8_t* Wcur, const uint8_t* Wnext,
                                         float (&acc)[2][8][4],
                                         int m0, int n0, int lane, int tid, int (&wph)[2]) {
#pragma unroll
    for (int i = 0; i < 2; i++)
#pragma unroll
        for (int j = 0; j < 8; j++)
#pragma unroll
            for (int qq = 0; qq < 4; qq++) acc[i][j][qq] = 0.f;

    __syncthreads();  // order prior A-tile writes before compute
#pragma unroll 1
    for (int ck = 0; ck < 8; ck++) {
        int b = ck & 1;
        mbar_wait(sb + MBAR + b * 8, wph[b] & 1);
        wph[b] ^= 1;
        compute_chunk<LO>(sb, b, ck, acc, m0, n0, lane);
        __syncthreads();  // all warps done with buf b before refill
        if (ck < 6)       issue_copy(sb, b, Wcur + (size_t)(ck + 2) * CHUNK_BYTES, tid);
        else if (Wnext)   issue_copy(sb, b, Wnext + (size_t)(ck - 6) * CHUNK_BYTES, tid);
    }
}

// 2-limb store (GEMM1 input)
__device__ __forceinline__ void sts_split2(char* smem, int row, int k, float y0, float y1) {
    __half h0 = __float2half_rn(y0);
    __half l0 = __float2half_rn(y0 - __half2float(h0));
    __half h1 = __float2half_rn(y1);
    __half l1 = __float2half_rn(y1 - __half2float(h1));
    uint32_t off = row * ASTR_B + k * 2;
    *reinterpret_cast<__half2*>(smem + A_HI + off) = __halves2half2(h0, h1);
    *reinterpret_cast<__half2*>(smem + A_LO + off) = __halves2half2(l0, l1);
}
// single-limb store (GEMM2/3 inputs)
__device__ __forceinline__ void sts_single2(char* smem, int row, int k, float y0, float y1) {
    uint32_t off = row * ASTR_B + k * 2;
    *reinterpret_cast<__half2*>(smem + A_HI + off) =
        __halves2half2(__float2half_rn(y0), __float2half_rn(y1));
}

// ---------------------------------------------------------------------------
__global__ void __launch_bounds__(NTH, 2)
fused_mma(const float* __restrict__ x,
          const int* __restrict__ bids,
          const float* __restrict__ b2,
          const float* __restrict__ b3,
          float* __restrict__ out, int N) {
    extern __shared__ __align__(128) char smem[];
    const uint32_t sb = smem_u32(smem);
    const int tid = threadIdx.x;
    const int lane = tid & 31, w = tid >> 5;
    const int warp_m = w >> 2, warp_n = w & 3;    // 2 x 4 warps
    const int m0 = warp_m * 32, n0 = warp_n * 64;
    const int lgrp = lane >> 2, lq = lane & 3;
    const int row0 = blockIdx.x * TILE_M;

    if (tid == 0) {
        MBAR_INIT(sb + MBAR + 0, 1);
        MBAR_INIT(sb + MBAR + 8, 1);
    }
    __syncthreads();
    issue_copy(sb, 0, d_W1i, tid);
    issue_copy(sb, 1, d_W1i + CHUNK_BYTES, tid);

    // ---- build A (hi/lo fp16) from x tile [64 x 256] ----
#pragma unroll 4
    for (int i = 0; i < 16; i++) {
        int idx = tid + NTH * i;          // 4096 float4 groups
        int m = idx >> 6, c4 = idx & 63;
        int row = row0 + m;
        float4 v = (row < N) ? reinterpret_cast<const float4*>(x)[(size_t)row * 64 + c4]
                             : make_float4(0.f, 0.f, 0.f, 0.f);
        sts_split2(smem, m, c4 * 4 + 0, v.x, v.y);
        sts_split2(smem, m, c4 * 4 + 2, v.z, v.w);
    }

    float acc[2][8][4];
    int wph[2] = {0, 0};

    // ================= GEMM1 (2-limb A) + layernorm/FiLM/relu =================
    run_gemm<true>(sb, d_W1i, d_W2i, acc, m0, n0, lane, tid, wph);
    {
#pragma unroll
        for (int mi = 0; mi < 2; mi++)
#pragma unroll
            for (int half = 0; half < 2; half++) {
                float s = 0.f, ss = 0.f;
#pragma unroll
                for (int j = 0; j < 8; j++) {
                    float v0 = acc[mi][j][half * 2 + 0];
                    float v1 = acc[mi][j][half * 2 + 1];
                    s += v0 + v1;
                    ss = fmaf(v0, v0, fmaf(v1, v1, ss));
                }
                s  += __shfl_xor_sync(0xffffffffu, s, 1);
                s  += __shfl_xor_sync(0xffffffffu, s, 2);
                ss += __shfl_xor_sync(0xffffffffu, ss, 1);
                ss += __shfl_xor_sync(0xffffffffu, ss, 2);
                if (lq == 0) {
                    int r = m0 + mi * 16 + half * 8 + lgrp;
                    *reinterpret_cast<float2*>(smem + PART + (r * 4 + warp_n) * 8) =
                        make_float2(s, ss);
                }
            }
        __syncthreads();
        if (tid < TILE_M) {
            float s = 0.f, ss = 0.f;
#pragma unroll
            for (int qq = 0; qq < 4; qq++) {
                float2 p = *reinterpret_cast<float2*>(smem + PART + (tid * 4 + qq) * 8);
                s += p.x;
                ss += p.y;
            }
            float mu = s * (1.f / 256.f);
            float var = ss * (1.f / 256.f) - mu * mu;
            float rstd = rsqrtf(var + 1e-5f);
            *reinterpret_cast<float2*>(smem + STAT + tid * 8) = make_float2(mu, rstd);
            int row = row0 + tid;
            *reinterpret_cast<int*>(smem + SBID + tid * 4) = (row < N) ? bids[row] : 0;
        }
        __syncthreads();
#pragma unroll
        for (int mi = 0; mi < 2; mi++)
#pragma unroll
            for (int half = 0; half < 2; half++) {
                int r = m0 + mi * 16 + half * 8 + lgrp;
                float2 st = *reinterpret_cast<float2*>(smem + STAT + r * 8);
                int bid = *reinterpret_cast<int*>(smem + SBID + r * 4);
                const float* gp = d_GAMMA + (size_t)bid * H_DIM;
                const float* bp = d_BETA  + (size_t)bid * H_DIM;
#pragma unroll
                for (int j = 0; j < 8; j++) {
                    int c = n0 + j * 8 + lq * 2;
                    float2 g2 = *reinterpret_cast<const float2*>(gp + c);
                    float2 be = *reinterpret_cast<const float2*>(bp + c);
                    float y0 = fmaxf(fmaf((acc[mi][j][half * 2 + 0] - st.x) * st.y, g2.x, be.x), 0.f);
                    float y1 = fmaxf(fmaf((acc[mi][j][half * 2 + 1] - st.x) * st.y, g2.y, be.y), 0.f);
                    sts_single2(smem, r, c, y0, y1);
                }
            }
    }

    // ================= GEMM2 (single A) + relu + b2 =================
    run_gemm<false>(sb, d_W2i, d_W3i, acc, m0, n0, lane, tid, wph);
    {
#pragma unroll
        for (int mi = 0; mi < 2; mi++)
#pragma unroll
            for (int half = 0; half < 2; half++) {
                int r = m0 + mi * 16 + half * 8 + lgrp;
#pragma unroll
                for (int j = 0; j < 8; j++) {
                    int c = n0 + j * 8 + lq * 2;
                    float2 bb = *reinterpret_cast<const float2*>(b2 + c);
                    float y0 = fmaxf(acc[mi][j][half * 2 + 0] + bb.x, 0.f);
                    float y1 = fmaxf(acc[mi][j][half * 2 + 1] + bb.y, 0.f);
                    sts_single2(smem, r, c, y0, y1);
                }
            }
    }

    // ================= GEMM3 (single A, two 256-col halves) + b3 -> out =====
#pragma unroll 1
    for (int hf = 0; hf < 2; hf++) {
        const uint8_t* Wnext = (hf == 0) ? d_W3i + 131072 : nullptr;
        run_gemm<false>(sb, d_W3i + (size_t)hf * 131072, Wnext, acc, m0, n0, lane, tid, wph);
#pragma unroll
        for (int mi = 0; mi < 2; mi++)
#pragma unroll
            for (int half = 0; half < 2; half++) {
                int r = m0 + mi * 16 + half * 8 + lgrp;
                int row = row0 + r;
                if (row < N) {
                    float* op = out + (size_t)row * OUT_DIM + hf * 256;
#pragma unroll
                    for (int j = 0; j < 8; j++) {
                        int c = n0 + j * 8 + lq * 2;
                        float2 bb = *reinterpret_cast<const float2*>(b3 + hf * 256 + c);
                        float2 o2;
                        o2.x = acc[mi][j][half * 2 + 0] + bb.x;
                        o2.y = acc[mi][j][half * 2 + 1] + bb.y;
                        *reinterpret_cast<float2*>(op + c) = o2;
                    }
                }
            }
    }
}

// ---------------------------------------------------------------------------
extern "C" void kernel_launch(void* const* d_in, const int* in_sizes, int n_in,
                              void* d_out, int out_size) {
    const float* x         = (const float*)d_in[0];
    const float* cond      = (const float*)d_in[1];
    const int*   batch_ids = (const int*)  d_in[2];
    const float* v_cond    = (const float*)d_in[3];
    const float* g_cond    = (const float*)d_in[4];
    const float* b_cond    = (const float*)d_in[5];
    const float* v1        = (const float*)d_in[6];
    const float* g1        = (const float*)d_in[7];
    const float* v2        = (const float*)d_in[8];
    const float* g2        = (const float*)d_in[9];
    const float* b2        = (const float*)d_in[10];
    const float* v3        = (const float*)d_in[11];
    const float* g3        = (const float*)d_in[12];
    const float* b3        = (const float*)d_in[13];
    float* out = (float*)d_out;

    int N = in_sizes[0] / K_DIM;

    wn_kernel<<<OUT_DIM, 256>>>(v_cond, g_cond, 0);
    wn_kernel<<<H_DIM,   256>>>(v1, g1, 1);
    wn_kernel<<<H_DIM,   256>>>(v2, g2, 2);
    wn_kernel<<<OUT_DIM, 256>>>(v3, g3, 3);
    film_kernel<<<G_DIM, 256>>>(cond, b_cond);

    cudaFuncSetAttribute(fused_mma, cudaFuncAttributeMaxDynamicSharedMemorySize, SMEM_TOTAL);
    int grid = (N + TILE_M - 1) / TILE_M;
    fused_mma<<<grid, NTH, SMEM_TOTAL>>>(x, batch_ids, b2, b3, out, N);
}

// round 12
// speedup vs baseline: 4.9709x; 1.1427x over previous
#include <cuda_runtime.h>
#include <cuda_fp16.h>
#include <math.h>
#include <stdint.h>

#define K_DIM 256
#define H_DIM 256
#define OUT_DIM 512
#define G_DIM 256
#define TILE_M 64
#define NTH 256
#define CHUNK_BYTES 16384     // one k32 chunk: 256 n-rows x 64B fp16
#define NBUF 4
#define NCHUNKS 32            // 4 GEMM passes x 8 chunks

// ---- smem layout (bytes) ----
#define ASTR_B 528            // 264 fp16 per A row
#define MBAR 0                // 4 mbarriers
#define A_HI 1024
#define WB   (A_HI + 33792)   // 34816 (128B aligned)
#define PART (WB + NBUF * CHUNK_BYTES)  // 100352: 64 rows x 4 warps x float2
#define STAT (PART + 2048)    // 102400: 64 x float2
#define SBID (STAT + 512)     // 102912: 64 x int
#define SMEM_TOTAL 103168

// ---------------- global scratch ----------------
__device__ float d_Wc[OUT_DIM * K_DIM];
__device__ float d_GAMMA[G_DIM * H_DIM];
__device__ float d_BETA[G_DIM * H_DIM];
__device__ __align__(128) uint8_t d_W1i[131072];
__device__ __align__(128) uint8_t d_W2i[131072];
__device__ __align__(128) uint8_t d_W3i[262144];

// ---------------- asm helpers ----------------
__device__ __forceinline__ uint32_t smem_u32(const void* p) {
    uint32_t a;
    asm("{ .reg .u64 t; cvta.to.shared.u64 t, %1; cvt.u32.u64 %0, t; }" : "=r"(a) : "l"(p));
    return a;
}
__device__ __forceinline__ void ldsm4(uint32_t (&r)[4], uint32_t a) {
    asm volatile("ldmatrix.sync.aligned.m8n8.x4.shared.b16 {%0,%1,%2,%3}, [%4];"
                 : "=r"(r[0]), "=r"(r[1]), "=r"(r[2]), "=r"(r[3]) : "r"(a));
}
__device__ __forceinline__ void mma16816(float* c, const uint32_t* a, uint32_t b0, uint32_t b1) {
    asm volatile("mma.sync.aligned.m16n8k16.row.col.f32.f16.f16.f32 "
                 "{%0,%1,%2,%3}, {%4,%5,%6,%7}, {%8,%9}, {%0,%1,%2,%3};"
                 : "+f"(c[0]), "+f"(c[1]), "+f"(c[2]), "+f"(c[3])
                 : "r"(a[0]), "r"(a[1]), "r"(a[2]), "r"(a[3]), "r"(b0), "r"(b1));
}
#define MBAR_INIT(mb, c) asm volatile("mbarrier.init.shared.b64 [%0], %1;" :: "r"(mb), "r"(c) : "memory")
__device__ __forceinline__ void mbar_wait(uint32_t mb, uint32_t parity) {
    asm volatile(
        "{\n\t.reg .pred P1;\n\tW_%=:\n\t"
        "mbarrier.try_wait.parity.acquire.cta.shared::cta.b64 P1, [%0], %1, 0x989680;\n\t"
        "@P1 bra.uni D_%=;\n\tbra.uni W_%=;\n\tD_%=:\n\t}"
        :: "r"(mb), "r"(parity) : "memory");
}
// flat chunk index -> global source
__device__ __forceinline__ const uint8_t* chunk_src(int flat) {
    int img = flat >> 3, ck = flat & 7;
    const uint8_t* base = (img == 0) ? d_W1i : (img == 1) ? d_W2i
                         : (img == 2) ? d_W3i : (d_W3i + 131072);
    return base + (size_t)ck * CHUNK_BYTES;
}
__device__ __forceinline__ void issue_copy_flat(uint32_t sb, int flat, int tid) {
    if (tid == 0 && flat < NCHUNKS) {
        int buf = flat & (NBUF - 1);
        uint32_t mb = sb + MBAR + buf * 8;
        asm volatile("mbarrier.arrive.expect_tx.shared.b64 _, [%0], %1;"
                     :: "r"(mb), "r"(CHUNK_BYTES) : "memory");
        asm volatile("cp.async.bulk.shared::cta.global.mbarrier::complete_tx::bytes "
                     "[%0], [%1], %2, [%3];"
                     :: "r"(sb + WB + buf * CHUNK_BYTES), "l"(chunk_src(flat)),
                        "r"(CHUNK_BYTES), "r"(mb)
                     : "memory");
    }
}

// ---------------------------------------------------------------------------
// prep kernels
// ---------------------------------------------------------------------------
__global__ void wn_kernel(const float* __restrict__ v, const float* __restrict__ g, int which) {
    int r = blockIdx.x, t = threadIdx.x;
    float x = v[r * K_DIM + t];
    float ss = x * x;
#pragma unroll
    for (int o = 16; o; o >>= 1) ss += __shfl_xor_sync(0xffffffffu, ss, o);
    __shared__ float red[8];
    __shared__ float s_scale;
    if ((t & 31) == 0) red[t >> 5] = ss;
    __syncthreads();
    if (t == 0) {
        float tot = 0.f;
#pragma unroll
        for (int i = 0; i < 8; i++) tot += red[i];
        s_scale = g[r] / sqrtf(tot);
    }
    __syncthreads();
    float wv = x * s_scale;
    if (which == 0) { d_Wc[r * K_DIM + t] = wv; return; }
    uint8_t* img = (which == 1) ? d_W1i : (which == 2) ? d_W2i : d_W3i;
    int p = r >> 8, n = r & 255;
    img += (size_t)p * 131072;
    int ck = t >> 5, kk = t & 31, q = kk >> 3, e = kk & 7;
    int qs = (q + (n >> 1)) & 3;
    size_t off = (size_t)ck * CHUNK_BYTES + n * 64 + qs * 16 + e * 2;
    *reinterpret_cast<__half*>(img + off) = __float2half(wv);
}

__global__ void film_kernel(const float* __restrict__ cond, const float* __restrict__ b_cond) {
    __shared__ float cs[K_DIM];
    int g = blockIdx.x, t = threadIdx.x;
    cs[t] = cond[g * K_DIM + t];
    __syncthreads();
    const float* w0 = d_Wc + (size_t)t * K_DIM;
    const float* w1 = d_Wc + (size_t)(t + 256) * K_DIM;
    float a0 = 0.f, a1 = 0.f;
#pragma unroll 8
    for (int k = 0; k < K_DIM; k++) {
        float c = cs[k];
        a0 = fmaf(c, w0[k], a0);
        a1 = fmaf(c, w1[k], a1);
    }
    d_GAMMA[g * H_DIM + t] = a0 + b_cond[t] + 1.0f;
    d_BETA[g * H_DIM + t]  = a1 + b_cond[t + 256];
}

// ---------------------------------------------------------------------------
// one k32 chunk, single fp16 A
// ---------------------------------------------------------------------------
__device__ __forceinline__ void compute_chunk(uint32_t sb, int buf, int ck,
                                              float (&acc)[2][8][4],
                                              int m0, int n0, int lane) {
    const uint32_t arow = m0 + (lane & 15);
    const uint32_t koff = (lane >> 4) * 8;
    const uint32_t wbase = sb + WB + buf * CHUNK_BYTES;
#pragma unroll
    for (int s = 0; s < 32; s += 16) {
        const int kg = ck * 32 + s;
        uint32_t ah0[4], ah1[4];
        uint32_t aoff = arow * ASTR_B + (kg + koff) * 2;
        ldsm4(ah0, sb + A_HI + aoff);
        ldsm4(ah1, sb + A_HI + aoff + 16 * ASTR_B);
        const uint32_t q = (uint32_t)(s >> 3) + (lane >> 4);
        uint32_t wf[4][4];
#pragma unroll
        for (int g = 0; g < 4; g++) {
            uint32_t nr = n0 + g * 16 + (lane & 15);
            ldsm4(wf[g], wbase + nr * 64 + (((q + (nr >> 1)) & 3) << 4));
        }
#pragma unroll
        for (int g = 0; g < 4; g++) {
            mma16816(acc[0][2 * g + 0], ah0, wf[g][0], wf[g][2]);
            mma16816(acc[0][2 * g + 1], ah0, wf[g][1], wf[g][3]);
            mma16816(acc[1][2 * g + 0], ah1, wf[g][0], wf[g][2]);
            mma16816(acc[1][2 * g + 1], ah1, wf[g][1], wf[g][3]);
        }
    }
}

// full GEMM over K=256 (8 chunks) from the 4-deep ring; flatbase = pass*8
__device__ __forceinline__ void run_gemm(uint32_t sb, int flatbase,
                                         float (&acc)[2][8][4],
                                         int m0, int n0, int lane, int tid) {
#pragma unroll
    for (int i = 0; i < 2; i++)
#pragma unroll
        for (int j = 0; j < 8; j++)
#pragma unroll
            for (int qq = 0; qq < 4; qq++) acc[i][j][qq] = 0.f;

    __syncthreads();  // order prior A-tile writes before compute
#pragma unroll 1
    for (int ck = 0; ck < 8; ck++) {
        int flat = flatbase + ck;
        int b = flat & (NBUF - 1);
        mbar_wait(sb + MBAR + b * 8, (flat >> 2) & 1);
        compute_chunk(sb, b, ck, acc, m0, n0, lane);
        __syncthreads();  // all warps done with buf b before refill
        issue_copy_flat(sb, flat + NBUF, tid);
    }
}

// single-limb fp16 store into A at (row, k pair)
__device__ __forceinline__ void sts_single2(char* smem, int row, int k, float y0, float y1) {
    uint32_t off = row * ASTR_B + k * 2;
    *reinterpret_cast<__half2*>(smem + A_HI + off) =
        __halves2half2(__float2half_rn(y0), __float2half_rn(y1));
}

// ---------------------------------------------------------------------------
__global__ void __launch_bounds__(NTH, 2)
fused_mma(const float* __restrict__ x,
          const int* __restrict__ bids,
          const float* __restrict__ b2,
          const float* __restrict__ b3,
          float* __restrict__ out, int N) {
    extern __shared__ __align__(128) char smem[];
    const uint32_t sb = smem_u32(smem);
    const int tid = threadIdx.x;
    const int lane = tid & 31, w = tid >> 5;
    const int warp_m = w >> 2, warp_n = w & 3;    // 2 x 4 warps
    const int m0 = warp_m * 32, n0 = warp_n * 64;
    const int lgrp = lane >> 2, lq = lane & 3;
    const int row0 = blockIdx.x * TILE_M;

    if (tid == 0) {
#pragma unroll
        for (int b = 0; b < NBUF; b++) MBAR_INIT(sb + MBAR + b * 8, 1);
    }
    __syncthreads();
#pragma unroll
    for (int f = 0; f < NBUF; f++) issue_copy_flat(sb, f, tid);

    // ---- build A (single fp16) from x tile [64 x 256] ----
#pragma unroll 4
    for (int i = 0; i < 16; i++) {
        int idx = tid + NTH * i;          // 4096 float4 groups
        int m = idx >> 6, c4 = idx & 63;
        int row = row0 + m;
        float4 v = (row < N) ? reinterpret_cast<const float4*>(x)[(size_t)row * 64 + c4]
                             : make_float4(0.f, 0.f, 0.f, 0.f);
        sts_single2(smem, m, c4 * 4 + 0, v.x, v.y);
        sts_single2(smem, m, c4 * 4 + 2, v.z, v.w);
    }

    float acc[2][8][4];

    // ================= GEMM1 + layernorm/FiLM/relu =================
    run_gemm(sb, 0, acc, m0, n0, lane, tid);
    {
#pragma unroll
        for (int mi = 0; mi < 2; mi++)
#pragma unroll
            for (int half = 0; half < 2; half++) {
                float s = 0.f, ss = 0.f;
#pragma unroll
                for (int j = 0; j < 8; j++) {
                    float v0 = acc[mi][j][half * 2 + 0];
                    float v1 = acc[mi][j][half * 2 + 1];
                    s += v0 + v1;
                    ss = fmaf(v0, v0, fmaf(v1, v1, ss));
                }
                s  += __shfl_xor_sync(0xffffffffu, s, 1);
                s  += __shfl_xor_sync(0xffffffffu, s, 2);
                ss += __shfl_xor_sync(0xffffffffu, ss, 1);
                ss += __shfl_xor_sync(0xffffffffu, ss, 2);
                if (lq == 0) {
                    int r = m0 + mi * 16 + half * 8 + lgrp;
                    *reinterpret_cast<float2*>(smem + PART + (r * 4 + warp_n) * 8) =
                        make_float2(s, ss);
                }
            }
        __syncthreads();
        if (tid < TILE_M) {
            float s = 0.f, ss = 0.f;
#pragma unroll
            for (int qq = 0; qq < 4; qq++) {
                float2 p = *reinterpret_cast<float2*>(smem + PART + (tid * 4 + qq) * 8);
                s += p.x;
                ss += p.y;
            }
            float mu = s * (1.f / 256.f);
            float var = ss * (1.f / 256.f) - mu * mu;
            float rstd = rsqrtf(var + 1e-5f);
            *reinterpret_cast<float2*>(smem + STAT + tid * 8) = make_float2(mu, rstd);
            int row = row0 + tid;
            *reinterpret_cast<int*>(smem + SBID + tid * 4) = (row < N) ? bids[row] : 0;
        }
        __syncthreads();
#pragma unroll
        for (int mi = 0; mi < 2; mi++)
#pragma unroll
            for (int half = 0; half < 2; half++) {
                int r = m0 + mi * 16 + half * 8 + lgrp;
                float2 st = *reinterpret_cast<float2*>(smem + STAT + r * 8);
                int bid = *reinterpret_cast<int*>(smem + SBID + r * 4);
                const float* gp = d_GAMMA + (size_t)bid * H_DIM;
                const float* bp = d_BETA  + (size_t)bid * H_DIM;
#pragma unroll
                for (int j = 0; j < 8; j++) {
                    int c = n0 + j * 8 + lq * 2;
                    float2 g2 = *reinterpret_cast<const float2*>(gp + c);
                    float2 be = *reinterpret_cast<const float2*>(bp + c);
                    float y0 = fmaxf(fmaf((acc[mi][j][half * 2 + 0] - st.x) * st.y, g2.x, be.x), 0.f);
                    float y1 = fmaxf(fmaf((acc[mi][j][half * 2 + 1] - st.x) * st.y, g2.y, be.y), 0.f);
                    sts_single2(smem, r, c, y0, y1);
                }
            }
    }

    // ================= GEMM2 + relu + b2 =================
    run_gemm(sb, 8, acc, m0, n0, lane, tid);
    {
#pragma unroll
        for (int mi = 0; mi < 2; mi++)
#pragma unroll
            for (int half = 0; half < 2; half++) {
                int r = m0 + mi * 16 + half * 8 + lgrp;
#pragma unroll
                for (int j = 0; j < 8; j++) {
                    int c = n0 + j * 8 + lq * 2;
                    float2 bb = *reinterpret_cast<const float2*>(b2 + c);
                    float y0 = fmaxf(acc[mi][j][half * 2 + 0] + bb.x, 0.f);
                    float y1 = fmaxf(acc[mi][j][half * 2 + 1] + bb.y, 0.f);
                    sts_single2(smem, r, c, y0, y1);
                }
            }
    }

    // ================= GEMM3 (two 256-col halves) + b3 -> out =====
#pragma unroll 1
    for (int hf = 0; hf < 2; hf++) {
        run_gemm(sb, 16 + hf * 8, acc, m0, n0, lane, tid);
#pragma unroll
        for (int mi = 0; mi < 2; mi++)
#pragma unroll
            for (int half = 0; half < 2; half++) {
                int r = m0 + mi * 16 + half * 8 + lgrp;
                int row = row0 + r;
                if (row < N) {
                    float* op = out + (size_t)row * OUT_DIM + hf * 256;
#pragma unroll
                    for (int j = 0; j < 8; j++) {
                        int c = n0 + j * 8 + lq * 2;
                        float2 bb = *reinterpret_cast<const float2*>(b3 + hf * 256 + c);
                        float2 o2;
                        o2.x = acc[mi][j][half * 2 + 0] + bb.x;
                        o2.y = acc[mi][j][half * 2 + 1] + bb.y;
                        *reinterpret_cast<float2*>(op + c) = o2;
                    }
                }
            }
    }
}

// ---------------------------------------------------------------------------
extern "C" void kernel_launch(void* const* d_in, const int* in_sizes, int n_in,
                              void* d_out, int out_size) {
    const float* x         = (const float*)d_in[0];
    const float* cond      = (const float*)d_in[1];
    const int*   batch_ids = (const int*)  d_in[2];
    const float* v_cond    = (const float*)d_in[3];
    const float* g_cond    = (const float*)d_in[4];
    const float* b_cond    = (const float*)d_in[5];
    const float* v1        = (const float*)d_in[6];
    const float* g1        = (const float*)d_in[7];
    const float* v2        = (const float*)d_in[8];
    const float* g2        = (const float*)d_in[9];
    const float* b2        = (const float*)d_in[10];
    const float* v3        = (const float*)d_in[11];
    const float* g3        = (const float*)d_in[12];
    const float* b3        = (const float*)d_in[13];
    float* out = (float*)d_out;

    int N = in_sizes[0] / K_DIM;

    wn_kernel<<<OUT_DIM, 256>>>(v_cond, g_cond, 0);
    wn_kernel<<<H_DIM,   256>>>(v1, g1, 1);
    wn_kernel<<<H_DIM,   256>>>(v2, g2, 2);
    wn_kernel<<<OUT_DIM, 256>>>(v3, g3, 3);
    film_kernel<<<G_DIM, 256>>>(cond, b_cond);

    cudaFuncSetAttribute(fused_mma, cudaFuncAttributeMaxDynamicSharedMemorySize, SMEM_TOTAL);
    int grid = (N + TILE_M - 1) / TILE_M;
    fused_mma<<<grid, NTH, SMEM_TOTAL>>>(x, batch_ids, b2, b3, out, N);
}

// round 13
// speedup vs baseline: 5.0238x; 1.0106x over previous
#include <cuda_runtime.h>
#include <cuda_fp16.h>
#include <math.h>
#include <stdint.h>

#define K_DIM 256
#define H_DIM 256
#define OUT_DIM 512
#define G_DIM 256
#define TILE_M 64
#define NTH 256
#define NWARP 8
#define CHUNK_BYTES 16384     // one k32 chunk: 256 n-rows x 64B fp16
#define NBUF 4
#define NCHUNKS 32            // 4 GEMM passes x 8 chunks

// ---- smem layout (bytes) ----
#define ASTR_B 528            // 264 fp16 per A row
#define MBAR 0                // full[4] @ +0..31, empty[4] @ +32..63
#define A_HI 1024
#define WB   (A_HI + 33792)   // 34816 (128B aligned)
#define PART (WB + NBUF * CHUNK_BYTES)  // 100352
#define STAT (PART + 2048)    // 102400
#define SBID (STAT + 512)     // 102912
#define SMEM_TOTAL 103168

// ---------------- global scratch ----------------
__device__ float d_Wc[OUT_DIM * K_DIM];
__device__ float d_GAMMA[G_DIM * H_DIM];
__device__ float d_BETA[G_DIM * H_DIM];
__device__ __align__(128) uint8_t d_W1i[131072];
__device__ __align__(128) uint8_t d_W2i[131072];
__device__ __align__(128) uint8_t d_W3i[262144];

// ---------------- asm helpers ----------------
__device__ __forceinline__ uint32_t smem_u32(const void* p) {
    uint32_t a;
    asm("{ .reg .u64 t; cvta.to.shared.u64 t, %1; cvt.u32.u64 %0, t; }" : "=r"(a) : "l"(p));
    return a;
}
__device__ __forceinline__ void ldsm4(uint32_t (&r)[4], uint32_t a) {
    asm volatile("ldmatrix.sync.aligned.m8n8.x4.shared.b16 {%0,%1,%2,%3}, [%4];"
                 : "=r"(r[0]), "=r"(r[1]), "=r"(r[2]), "=r"(r[3]) : "r"(a));
}
__device__ __forceinline__ void mma16816(float* c, const uint32_t* a, uint32_t b0, uint32_t b1) {
    asm volatile("mma.sync.aligned.m16n8k16.row.col.f32.f16.f16.f32 "
                 "{%0,%1,%2,%3}, {%4,%5,%6,%7}, {%8,%9}, {%0,%1,%2,%3};"
                 : "+f"(c[0]), "+f"(c[1]), "+f"(c[2]), "+f"(c[3])
                 : "r"(a[0]), "r"(a[1]), "r"(a[2]), "r"(a[3]), "r"(b0), "r"(b1));
}
#define MBAR_INIT(mb, c) asm volatile("mbarrier.init.shared.b64 [%0], %1;" :: "r"(mb), "r"(c) : "memory")
#define MBAR_ARRIVE(mb)  asm volatile("mbarrier.arrive.shared.b64 _, [%0];" :: "r"(mb) : "memory")
__device__ __forceinline__ void mbar_wait(uint32_t mb, uint32_t parity) {
    asm volatile(
        "{\n\t.reg .pred P1;\n\tW_%=:\n\t"
        "mbarrier.try_wait.parity.acquire.cta.shared::cta.b64 P1, [%0], %1, 0x989680;\n\t"
        "@P1 bra.uni D_%=;\n\tbra.uni W_%=;\n\tD_%=:\n\t}"
        :: "r"(mb), "r"(parity) : "memory");
}
// flat chunk index -> global source
__device__ __forceinline__ const uint8_t* chunk_src(int flat) {
    int img = flat >> 3, ck = flat & 7;
    const uint8_t* base = (img == 0) ? d_W1i : (img == 1) ? d_W2i
                         : (img == 2) ? d_W3i : (d_W3i + 131072);
    return base + (size_t)ck * CHUNK_BYTES;
}
// producer: wait buffer drained (rounds of 4), then issue bulk copy
__device__ __forceinline__ void issue_copy_flat(uint32_t sb, int flat, int tid) {
    if (tid == 0 && flat < NCHUNKS) {
        int buf = flat & (NBUF - 1);
        uint32_t fullmb = sb + MBAR + buf * 8;
        if (flat >= NBUF) {
            // wait consumption of flat-NBUF (round (flat>>2)-1)
            mbar_wait(sb + MBAR + 32 + buf * 8, (((flat >> 2) + 1) & 1));
        }
        asm volatile("mbarrier.arrive.expect_tx.shared.b64 _, [%0], %1;"
                     :: "r"(fullmb), "r"(CHUNK_BYTES) : "memory");
        asm volatile("cp.async.bulk.shared::cta.global.mbarrier::complete_tx::bytes "
                     "[%0], [%1], %2, [%3];"
                     :: "r"(sb + WB + buf * CHUNK_BYTES), "l"(chunk_src(flat)),
                        "r"(CHUNK_BYTES), "r"(fullmb)
                     : "memory");
    }
}

// ---------------------------------------------------------------------------
// prep kernels
// ---------------------------------------------------------------------------
__global__ void wn_kernel(const float* __restrict__ v, const float* __restrict__ g, int which) {
    int r = blockIdx.x, t = threadIdx.x;
    float x = v[r * K_DIM + t];
    float ss = x * x;
#pragma unroll
    for (int o = 16; o; o >>= 1) ss += __shfl_xor_sync(0xffffffffu, ss, o);
    __shared__ float red[8];
    __shared__ float s_scale;
    if ((t & 31) == 0) red[t >> 5] = ss;
    __syncthreads();
    if (t == 0) {
        float tot = 0.f;
#pragma unroll
        for (int i = 0; i < 8; i++) tot += red[i];
        s_scale = g[r] / sqrtf(tot);
    }
    __syncthreads();
    float wv = x * s_scale;
    if (which == 0) { d_Wc[r * K_DIM + t] = wv; return; }
    uint8_t* img = (which == 1) ? d_W1i : (which == 2) ? d_W2i : d_W3i;
    int p = r >> 8, n = r & 255;
    img += (size_t)p * 131072;
    int ck = t >> 5, kk = t & 31, q = kk >> 3, e = kk & 7;
    int qs = (q + (n >> 1)) & 3;
    size_t off = (size_t)ck * CHUNK_BYTES + n * 64 + qs * 16 + e * 2;
    *reinterpret_cast<__half*>(img + off) = __float2half(wv);
}

__global__ void film_kernel(const float* __restrict__ cond, const float* __restrict__ b_cond) {
    __shared__ float cs[K_DIM];
    int g = blockIdx.x, t = threadIdx.x;
    cs[t] = cond[g * K_DIM + t];
    __syncthreads();
    const float* w0 = d_Wc + (size_t)t * K_DIM;
    const float* w1 = d_Wc + (size_t)(t + 256) * K_DIM;
    float a0 = 0.f, a1 = 0.f;
#pragma unroll 8
    for (int k = 0; k < K_DIM; k++) {
        float c = cs[k];
        a0 = fmaf(c, w0[k], a0);
        a1 = fmaf(c, w1[k], a1);
    }
    d_GAMMA[g * H_DIM + t] = a0 + b_cond[t] + 1.0f;
    d_BETA[g * H_DIM + t]  = a1 + b_cond[t + 256];
}

// ---------------------------------------------------------------------------
// one k32 chunk, single fp16 A
// ---------------------------------------------------------------------------
__device__ __forceinline__ void compute_chunk(uint32_t sb, int buf, int ck,
                                              float (&acc)[2][8][4],
                                              int m0, int n0, int lane) {
    const uint32_t arow = m0 + (lane & 15);
    const uint32_t koff = (lane >> 4) * 8;
    const uint32_t wbase = sb + WB + buf * CHUNK_BYTES;
#pragma unroll
    for (int s = 0; s < 32; s += 16) {
        const int kg = ck * 32 + s;
        uint32_t ah0[4], ah1[4];
        uint32_t aoff = arow * ASTR_B + (kg + koff) * 2;
        ldsm4(ah0, sb + A_HI + aoff);
        ldsm4(ah1, sb + A_HI + aoff + 16 * ASTR_B);
        const uint32_t q = (uint32_t)(s >> 3) + (lane >> 4);
        uint32_t wf[4][4];
#pragma unroll
        for (int g = 0; g < 4; g++) {
            uint32_t nr = n0 + g * 16 + (lane & 15);
            ldsm4(wf[g], wbase + nr * 64 + (((q + (nr >> 1)) & 3) << 4));
        }
#pragma unroll
        for (int g = 0; g < 4; g++) {
            mma16816(acc[0][2 * g + 0], ah0, wf[g][0], wf[g][2]);
            mma16816(acc[0][2 * g + 1], ah0, wf[g][1], wf[g][3]);
            mma16816(acc[1][2 * g + 0], ah1, wf[g][0], wf[g][2]);
            mma16816(acc[1][2 * g + 1], ah1, wf[g][1], wf[g][3]);
        }
    }
}

// full GEMM over K=256 (8 chunks), barrier-free ring hand-off
__device__ __forceinline__ void run_gemm(uint32_t sb, int flatbase,
                                         float (&acc)[2][8][4],
                                         int m0, int n0, int lane, int tid) {
#pragma unroll
    for (int i = 0; i < 2; i++)
#pragma unroll
        for (int j = 0; j < 8; j++)
#pragma unroll
            for (int qq = 0; qq < 4; qq++) acc[i][j][qq] = 0.f;

    __syncthreads();  // A-tile ready; also re-aligns warps at pass entry
#pragma unroll 1
    for (int ck = 0; ck < 8; ck++) {
        int flat = flatbase + ck;
        int b = flat & (NBUF - 1);
        mbar_wait(sb + MBAR + b * 8, (flat >> 2) & 1);   // full[b]
        compute_chunk(sb, b, ck, acc, m0, n0, lane);
        if (lane == 0) MBAR_ARRIVE(sb + MBAR + 32 + b * 8);  // empty[b], count 8
        issue_copy_flat(sb, flat + NBUF, tid);
    }
}

// single-limb fp16 store into A at (row, k pair)
__device__ __forceinline__ void sts_single2(char* smem, int row, int k, float y0, float y1) {
    uint32_t off = row * ASTR_B + k * 2;
    *reinterpret_cast<__half2*>(smem + A_HI + off) =
        __halves2half2(__float2half_rn(y0), __float2half_rn(y1));
}

// ---------------------------------------------------------------------------
__global__ void __launch_bounds__(NTH, 2)
fused_mma(const float* __restrict__ x,
          const int* __restrict__ bids,
          const float* __restrict__ b2,
          const float* __restrict__ b3,
          float* __restrict__ out, int N) {
    extern __shared__ __align__(128) char smem[];
    const uint32_t sb = smem_u32(smem);
    const int tid = threadIdx.x;
    const int lane = tid & 31, w = tid >> 5;
    const int warp_m = w >> 2, warp_n = w & 3;    // 2 x 4 warps
    const int m0 = warp_m * 32, n0 = warp_n * 64;
    const int lgrp = lane >> 2, lq = lane & 3;
    const int row0 = blockIdx.x * TILE_M;

    if (tid == 0) {
#pragma unroll
        for (int b = 0; b < NBUF; b++) {
            MBAR_INIT(sb + MBAR + b * 8, 1);           // full: tx-based
            MBAR_INIT(sb + MBAR + 32 + b * 8, NWARP);  // empty: one arrive per warp
        }
    }
    __syncthreads();
#pragma unroll
    for (int f = 0; f < NBUF; f++) issue_copy_flat(sb, f, tid);

    // ---- build A (single fp16) from x tile [64 x 256] ----
#pragma unroll 4
    for (int i = 0; i < 16; i++) {
        int idx = tid + NTH * i;
        int m = idx >> 6, c4 = idx & 63;
        int row = row0 + m;
        float4 v = (row < N) ? reinterpret_cast<const float4*>(x)[(size_t)row * 64 + c4]
                             : make_float4(0.f, 0.f, 0.f, 0.f);
        sts_single2(smem, m, c4 * 4 + 0, v.x, v.y);
        sts_single2(smem, m, c4 * 4 + 2, v.z, v.w);
    }

    float acc[2][8][4];

    // ================= GEMM1 + layernorm/FiLM/relu =================
    run_gemm(sb, 0, acc, m0, n0, lane, tid);
    {
#pragma unroll
        for (int mi = 0; mi < 2; mi++)
#pragma unroll
            for (int half = 0; half < 2; half++) {
                float s = 0.f, ss = 0.f;
#pragma unroll
                for (int j = 0; j < 8; j++) {
                    float v0 = acc[mi][j][half * 2 + 0];
                    float v1 = acc[mi][j][half * 2 + 1];
                    s += v0 + v1;
                    ss = fmaf(v0, v0, fmaf(v1, v1, ss));
                }
                s  += __shfl_xor_sync(0xffffffffu, s, 1);
                s  += __shfl_xor_sync(0xffffffffu, s, 2);
                ss += __shfl_xor_sync(0xffffffffu, ss, 1);
                ss += __shfl_xor_sync(0xffffffffu, ss, 2);
                if (lq == 0) {
                    int r = m0 + mi * 16 + half * 8 + lgrp;
                    *reinterpret_cast<float2*>(smem + PART + (r * 4 + warp_n) * 8) =
                        make_float2(s, ss);
                }
            }
        __syncthreads();   // all warps done with GEMM1 + partials published
        if (tid < TILE_M) {
            float s = 0.f, ss = 0.f;
#pragma unroll
            for (int qq = 0; qq < 4; qq++) {
                float2 p = *reinterpret_cast<float2*>(smem + PART + (tid * 4 + qq) * 8);
                s += p.x;
                ss += p.y;
            }
            float mu = s * (1.f / 256.f);
            float var = ss * (1.f / 256.f) - mu * mu;
            float rstd = rsqrtf(var + 1e-5f);
            *reinterpret_cast<float2*>(smem + STAT + tid * 8) = make_float2(mu, rstd);
            int row = row0 + tid;
            *reinterpret_cast<int*>(smem + SBID + tid * 4) = (row < N) ? bids[row] : 0;
        }
        __syncthreads();
#pragma unroll
        for (int mi = 0; mi < 2; mi++)
#pragma unroll
            for (int half = 0; half < 2; half++) {
                int r = m0 + mi * 16 + half * 8 + lgrp;
                float2 st = *reinterpret_cast<float2*>(smem + STAT + r * 8);
                int bid = *reinterpret_cast<int*>(smem + SBID + r * 4);
                const float* gp = d_GAMMA + (size_t)bid * H_DIM;
                const float* bp = d_BETA  + (size_t)bid * H_DIM;
#pragma unroll
                for (int j = 0; j < 8; j++) {
                    int c = n0 + j * 8 + lq * 2;
                    float2 g2 = *reinterpret_cast<const float2*>(gp + c);
                    float2 be = *reinterpret_cast<const float2*>(bp + c);
                    float y0 = fmaxf(fmaf((acc[mi][j][half * 2 + 0] - st.x) * st.y, g2.x, be.x), 0.f);
                    float y1 = fmaxf(fmaf((acc[mi][j][half * 2 + 1] - st.x) * st.y, g2.y, be.y), 0.f);
                    sts_single2(smem, r, c, y0, y1);
                }
            }
    }

    // ================= GEMM2 + relu + b2 =================
    run_gemm(sb, 8, acc, m0, n0, lane, tid);
    __syncthreads();   // all warps done reading A before epilogue overwrites it
    {
#pragma unroll
        for (int mi = 0; mi < 2; mi++)
#pragma unroll
            for (int half = 0; half < 2; half++) {
                int r = m0 + mi * 16 + half * 8 + lgrp;
#pragma unroll
                for (int j = 0; j < 8; j++) {
                    int c = n0 + j * 8 + lq * 2;
                    float2 bb = *reinterpret_cast<const float2*>(b2 + c);
                    float y0 = fmaxf(acc[mi][j][half * 2 + 0] + bb.x, 0.f);
                    float y1 = fmaxf(acc[mi][j][half * 2 + 1] + bb.y, 0.f);
                    sts_single2(smem, r, c, y0, y1);
                }
            }
    }

    // ================= GEMM3 (two 256-col halves) + b3 -> out =====
#pragma unroll 1
    for (int hf = 0; hf < 2; hf++) {
        run_gemm(sb, 16 + hf * 8, acc, m0, n0, lane, tid);
#pragma unroll
        for (int mi = 0; mi < 2; mi++)
#pragma unroll
            for (int half = 0; half < 2; half++) {
                int r = m0 + mi * 16 + half * 8 + lgrp;
                int row = row0 + r;
                if (row < N) {
                    float* op = out + (size_t)row * OUT_DIM + hf * 256;
#pragma unroll
                    for (int j = 0; j < 8; j++) {
                        int c = n0 + j * 8 + lq * 2;
                        float2 bb = *reinterpret_cast<const float2*>(b3 + hf * 256 + c);
                        float2 o2;
                        o2.x = acc[mi][j][half * 2 + 0] + bb.x;
                        o2.y = acc[mi][j][half * 2 + 1] + bb.y;
                        *reinterpret_cast<float2*>(op + c) = o2;
                    }
                }
            }
    }
}

// ---------------------------------------------------------------------------
extern "C" void kernel_launch(void* const* d_in, const int* in_sizes, int n_in,
                              void* d_out, int out_size) {
    const float* x         = (const float*)d_in[0];
    const float* cond      = (const float*)d_in[1];
    const int*   batch_ids = (const int*)  d_in[2];
    const float* v_cond    = (const float*)d_in[3];
    const float* g_cond    = (const float*)d_in[4];
    const float* b_cond    = (const float*)d_in[5];
    const float* v1        = (const float*)d_in[6];
    const float* g1        = (const float*)d_in[7];
    const float* v2        = (const float*)d_in[8];
    const float* g2        = (const float*)d_in[9];
    const float* b2        = (const float*)d_in[10];
    const float* v3        = (const float*)d_in[11];
    const float* g3        = (const float*)d_in[12];
    const float* b3        = (const float*)d_in[13];
    float* out = (float*)d_out;

    int N = in_sizes[0] / K_DIM;

    wn_kernel<<<OUT_DIM, 256>>>(v_cond, g_cond, 0);
    wn_kernel<<<H_DIM,   256>>>(v1, g1, 1);
    wn_kernel<<<H_DIM,   256>>>(v2, g2, 2);
    wn_kernel<<<OUT_DIM, 256>>>(v3, g3, 3);
    film_kernel<<<G_DIM, 256>>>(cond, b_cond);

    cudaFuncSetAttribute(fused_mma, cudaFuncAttributeMaxDynamicSharedMemorySize, SMEM_TOTAL);
    int grid = (N + TILE_M - 1) / TILE_M;
    fused_mma<<<grid, NTH, SMEM_TOTAL>>>(x, batch_ids, b2, b3, out, N);
}

// round 14
// speedup vs baseline: 5.0554x; 1.0063x over previous
#include <cuda_runtime.h>
#include <cuda_fp16.h>
#include <math.h>
#include <stdint.h>

#define K_DIM 256
#define H_DIM 256
#define OUT_DIM 512
#define G_DIM 256
#define TILE_M 64
#define NTH 256
#define NWARP 8
#define CHUNK_BYTES 16384     // one k32 chunk: 256 n-rows x 64B fp16
#define NBUF 4

// ---- smem layout (bytes) ----
#define ASTR_B 528            // 264 fp16 per A row
#define MBAR 0                // full[4] @ +0..31, empty[4] @ +32..63
#define A_HI 1024
#define WB   (A_HI + 33792)   // 34816 (128B aligned)
#define PART (WB + NBUF * CHUNK_BYTES)  // 100352
#define STAT (PART + 2048)    // 102400
#define SBID (STAT + 512)     // 102912
#define SMEM_TOTAL 103168

// ---------------- global scratch ----------------
__device__ float d_Wc[OUT_DIM * K_DIM];
__device__ float d_GAMMA[G_DIM * H_DIM];
__device__ float d_BETA[G_DIM * H_DIM];
__device__ __align__(128) uint8_t d_W1i[131072];
__device__ __align__(128) uint8_t d_W2i[131072];
__device__ __align__(128) uint8_t d_W3i[262144];

// ---------------- asm helpers ----------------
__device__ __forceinline__ uint32_t smem_u32(const void* p) {
    uint32_t a;
    asm("{ .reg .u64 t; cvta.to.shared.u64 t, %1; cvt.u32.u64 %0, t; }" : "=r"(a) : "l"(p));
    return a;
}
__device__ __forceinline__ void ldsm4(uint32_t (&r)[4], uint32_t a) {
    asm volatile("ldmatrix.sync.aligned.m8n8.x4.shared.b16 {%0,%1,%2,%3}, [%4];"
                 : "=r"(r[0]), "=r"(r[1]), "=r"(r[2]), "=r"(r[3]) : "r"(a));
}
__device__ __forceinline__ void mma16816(float* c, const uint32_t* a, uint32_t b0, uint32_t b1) {
    asm volatile("mma.sync.aligned.m16n8k16.row.col.f32.f16.f16.f32 "
                 "{%0,%1,%2,%3}, {%4,%5,%6,%7}, {%8,%9}, {%0,%1,%2,%3};"
                 : "+f"(c[0]), "+f"(c[1]), "+f"(c[2]), "+f"(c[3])
                 : "r"(a[0]), "r"(a[1]), "r"(a[2]), "r"(a[3]), "r"(b0), "r"(b1));
}
#define MBAR_INIT(mb, c) asm volatile("mbarrier.init.shared.b64 [%0], %1;" :: "r"(mb), "r"(c) : "memory")
#define MBAR_ARRIVE(mb)  asm volatile("mbarrier.arrive.shared.b64 _, [%0];" :: "r"(mb) : "memory")
__device__ __forceinline__ void mbar_wait(uint32_t mb, uint32_t parity) {
    asm volatile(
        "{\n\t.reg .pred P1;\n\tW_%=:\n\t"
        "mbarrier.try_wait.parity.acquire.cta.shared::cta.b64 P1, [%0], %1, 0x989680;\n\t"
        "@P1 bra.uni D_%=;\n\tbra.uni W_%=;\n\tD_%=:\n\t}"
        :: "r"(mb), "r"(parity) : "memory");
}
// flat chunk index (mod 32) -> global source
__device__ __forceinline__ const uint8_t* chunk_src(int flat) {
    int m = flat & 31;
    int img = m >> 3, ck = m & 7;
    const uint8_t* base = (img == 0) ? d_W1i : (img == 1) ? d_W2i
                         : (img == 2) ? d_W3i : (d_W3i + 131072);
    return base + (size_t)ck * CHUNK_BYTES;
}
// producer: wait buffer drained, then issue bulk copy (tid 0 only)
__device__ __forceinline__ void issue_copy_flat(uint32_t sb, int flat, int total, int tid) {
    if (tid == 0 && flat < total) {
        int buf = flat & (NBUF - 1);
        uint32_t fullmb = sb + MBAR + buf * 8;
        if (flat >= NBUF) {
            mbar_wait(sb + MBAR + 32 + buf * 8, (((flat >> 2) + 1) & 1));
        }
        asm volatile("mbarrier.arrive.expect_tx.shared.b64 _, [%0], %1;"
                     :: "r"(fullmb), "r"(CHUNK_BYTES) : "memory");
        asm volatile("cp.async.bulk.shared::cta.global.mbarrier::complete_tx::bytes "
                     "[%0], [%1], %2, [%3];"
                     :: "r"(sb + WB + buf * CHUNK_BYTES), "l"(chunk_src(flat)),
                        "r"(CHUNK_BYTES), "r"(fullmb)
                     : "memory");
    }
}

// ---------------------------------------------------------------------------
// prep: all four weight norms in one launch (grid 1536)
// blocks [0,512): Wc fp32; [512,768): W1; [768,1024): W2; [1024,1536): W3
// ---------------------------------------------------------------------------
__global__ void wn_all(const float* __restrict__ v_cond, const float* __restrict__ g_cond,
                       const float* __restrict__ v1, const float* __restrict__ g1,
                       const float* __restrict__ v2, const float* __restrict__ g2,
                       const float* __restrict__ v3, const float* __restrict__ g3) {
    int b = blockIdx.x, t = threadIdx.x;
    const float *v, *g;
    int which, r;
    if (b < 512)       { which = 0; r = b;        v = v_cond; g = g_cond; }
    else if (b < 768)  { which = 1; r = b - 512;  v = v1;     g = g1; }
    else if (b < 1024) { which = 2; r = b - 768;  v = v2;     g = g2; }
    else               { which = 3; r = b - 1024; v = v3;     g = g3; }

    float x = v[r * K_DIM + t];
    float ss = x * x;
#pragma unroll
    for (int o = 16; o; o >>= 1) ss += __shfl_xor_sync(0xffffffffu, ss, o);
    __shared__ float red[8];
    __shared__ float s_scale;
    if ((t & 31) == 0) red[t >> 5] = ss;
    __syncthreads();
    if (t == 0) {
        float tot = 0.f;
#pragma unroll
        for (int i = 0; i < 8; i++) tot += red[i];
        s_scale = g[r] / sqrtf(tot);
    }
    __syncthreads();
    float wv = x * s_scale;
    if (which == 0) { d_Wc[r * K_DIM + t] = wv; return; }
    uint8_t* img = (which == 1) ? d_W1i : (which == 2) ? d_W2i : d_W3i;
    int p = r >> 8, n = r & 255;
    img += (size_t)p * 131072;
    int ck = t >> 5, kk = t & 31, q = kk >> 3, e = kk & 7;
    int qs = (q + (n >> 1)) & 3;
    size_t off = (size_t)ck * CHUNK_BYTES + n * 64 + qs * 16 + e * 2;
    *reinterpret_cast<__half*>(img + off) = __float2half(wv);
}

__global__ void film_kernel(const float* __restrict__ cond, const float* __restrict__ b_cond) {
    __shared__ float cs[K_DIM];
    int g = blockIdx.x, t = threadIdx.x;
    cs[t] = cond[g * K_DIM + t];
    __syncthreads();
    const float* w0 = d_Wc + (size_t)t * K_DIM;
    const float* w1 = d_Wc + (size_t)(t + 256) * K_DIM;
    float a0 = 0.f, a1 = 0.f;
#pragma unroll 8
    for (int k = 0; k < K_DIM; k++) {
        float c = cs[k];
        a0 = fmaf(c, w0[k], a0);
        a1 = fmaf(c, w1[k], a1);
    }
    d_GAMMA[g * H_DIM + t] = a0 + b_cond[t] + 1.0f;
    d_BETA[g * H_DIM + t]  = a1 + b_cond[t + 256];
}

// ---------------------------------------------------------------------------
// one k32 chunk, single fp16 A
// ---------------------------------------------------------------------------
__device__ __forceinline__ void compute_chunk(uint32_t sb, int buf, int ck,
                                              float (&acc)[2][8][4],
                                              int m0, int n0, int lane) {
    const uint32_t arow = m0 + (lane & 15);
    const uint32_t koff = (lane >> 4) * 8;
    const uint32_t wbase = sb + WB + buf * CHUNK_BYTES;
#pragma unroll
    for (int s = 0; s < 32; s += 16) {
        const int kg = ck * 32 + s;
        uint32_t ah0[4], ah1[4];
        uint32_t aoff = arow * ASTR_B + (kg + koff) * 2;
        ldsm4(ah0, sb + A_HI + aoff);
        ldsm4(ah1, sb + A_HI + aoff + 16 * ASTR_B);
        const uint32_t q = (uint32_t)(s >> 3) + (lane >> 4);
        uint32_t wf[4][4];
#pragma unroll
        for (int g = 0; g < 4; g++) {
            uint32_t nr = n0 + g * 16 + (lane & 15);
            ldsm4(wf[g], wbase + nr * 64 + (((q + (nr >> 1)) & 3) << 4));
        }
#pragma unroll
        for (int g = 0; g < 4; g++) {
            mma16816(acc[0][2 * g + 0], ah0, wf[g][0], wf[g][2]);
            mma16816(acc[0][2 * g + 1], ah0, wf[g][1], wf[g][3]);
            mma16816(acc[1][2 * g + 0], ah1, wf[g][0], wf[g][2]);
            mma16816(acc[1][2 * g + 1], ah1, wf[g][1], wf[g][3]);
        }
    }
}

// full GEMM over K=256 (8 chunks) from the rolling ring
template <bool SYNC>
__device__ __forceinline__ void run_gemm(uint32_t sb, int flatbase, int total,
                                         float (&acc)[2][8][4],
                                         int m0, int n0, int lane, int tid) {
#pragma unroll
    for (int i = 0; i < 2; i++)
#pragma unroll
        for (int j = 0; j < 8; j++)
#pragma unroll
            for (int qq = 0; qq < 4; qq++) acc[i][j][qq] = 0.f;

    if (SYNC) __syncthreads();  // A-tile writes ordered before compute
#pragma unroll 1
    for (int ck = 0; ck < 8; ck++) {
        int flat = flatbase + ck;
        int b = flat & (NBUF - 1);
        mbar_wait(sb + MBAR + b * 8, (flat >> 2) & 1);       // full[b]
        compute_chunk(sb, b, ck, acc, m0, n0, lane);
        if (lane == 0) MBAR_ARRIVE(sb + MBAR + 32 + b * 8);  // empty[b]
        issue_copy_flat(sb, flat + NBUF, total, tid);
    }
}

// single-limb fp16 store into A at (row, k pair)
__device__ __forceinline__ void sts_single2(char* smem, int row, int k, float y0, float y1) {
    uint32_t off = row * ASTR_B + k * 2;
    *reinterpret_cast<__half2*>(smem + A_HI + off) =
        __halves2half2(__float2half_rn(y0), __float2half_rn(y1));
}

// ---------------------------------------------------------------------------
__global__ void __launch_bounds__(NTH, 2)
fused_mma(const float* __restrict__ x,
          const int* __restrict__ bids,
          const float* __restrict__ b2,
          const float* __restrict__ b3,
          float* __restrict__ out, int N, int ntiles) {
    extern __shared__ __align__(128) char smem[];
    const uint32_t sb = smem_u32(smem);
    const int tid = threadIdx.x;
    const int lane = tid & 31, w = tid >> 5;
    const int warp_m = w >> 2, warp_n = w & 3;    // 2 x 4 warps
    const int m0 = warp_m * 32, n0 = warp_n * 64;
    const int lgrp = lane >> 2, lq = lane & 3;
    const int grid = gridDim.x;

    // tiles handled by this CTA and total chunk budget
    const int my_nt = (ntiles - (int)blockIdx.x + grid - 1) / grid;
    if (my_nt <= 0) return;
    const int total = my_nt * 32;

    if (tid == 0) {
#pragma unroll
        for (int b = 0; b < NBUF; b++) {
            MBAR_INIT(sb + MBAR + b * 8, 1);           // full: tx-based
            MBAR_INIT(sb + MBAR + 32 + b * 8, NWARP);  // empty
        }
    }
    __syncthreads();
#pragma unroll
    for (int f = 0; f < NBUF; f++) issue_copy_flat(sb, f, total, tid);

    float acc[2][8][4];
    int flatbase = 0;

#pragma unroll 1
    for (int tile = blockIdx.x; tile < ntiles; tile += grid) {
        const int row0 = tile * TILE_M;

        // A free: first iter trivially; later iters all warps passed GEMM3 MMAs
        __syncthreads();

        // ---- build A (single fp16) from x tile [64 x 256] ----
#pragma unroll 4
        for (int i = 0; i < 16; i++) {
            int idx = tid + NTH * i;
            int m = idx >> 6, c4 = idx & 63;
            int row = row0 + m;
            float4 v = (row < N) ? reinterpret_cast<const float4*>(x)[(size_t)row * 64 + c4]
                                 : make_float4(0.f, 0.f, 0.f, 0.f);
            sts_single2(smem, m, c4 * 4 + 0, v.x, v.y);
            sts_single2(smem, m, c4 * 4 + 2, v.z, v.w);
        }

        // ================= GEMM1 + layernorm/FiLM/relu =================
        run_gemm<true>(sb, flatbase + 0, total, acc, m0, n0, lane, tid);
        {
#pragma unroll
            for (int mi = 0; mi < 2; mi++)
#pragma unroll
                for (int half = 0; half < 2; half++) {
                    float s = 0.f, ss = 0.f;
#pragma unroll
                    for (int j = 0; j < 8; j++) {
                        float v0 = acc[mi][j][half * 2 + 0];
                        float v1 = acc[mi][j][half * 2 + 1];
                        s += v0 + v1;
                        ss = fmaf(v0, v0, fmaf(v1, v1, ss));
                    }
                    s  += __shfl_xor_sync(0xffffffffu, s, 1);
                    s  += __shfl_xor_sync(0xffffffffu, s, 2);
                    ss += __shfl_xor_sync(0xffffffffu, ss, 1);
                    ss += __shfl_xor_sync(0xffffffffu, ss, 2);
                    if (lq == 0) {
                        int r = m0 + mi * 16 + half * 8 + lgrp;
                        *reinterpret_cast<float2*>(smem + PART + (r * 4 + warp_n) * 8) =
                            make_float2(s, ss);
                    }
                }
            __syncthreads();
            if (tid < TILE_M) {
                float s = 0.f, ss = 0.f;
#pragma unroll
                for (int qq = 0; qq < 4; qq++) {
                    float2 p = *reinterpret_cast<float2*>(smem + PART + (tid * 4 + qq) * 8);
                    s += p.x;
                    ss += p.y;
                }
                float mu = s * (1.f / 256.f);
                float var = ss * (1.f / 256.f) - mu * mu;
                float rstd = rsqrtf(var + 1e-5f);
                *reinterpret_cast<float2*>(smem + STAT + tid * 8) = make_float2(mu, rstd);
                int row = row0 + tid;
                *reinterpret_cast<int*>(smem + SBID + tid * 4) = (row < N) ? bids[row] : 0;
            }
            __syncthreads();
#pragma unroll
            for (int mi = 0; mi < 2; mi++)
#pragma unroll
                for (int half = 0; half < 2; half++) {
                    int r = m0 + mi * 16 + half * 8 + lgrp;
                    float2 st = *reinterpret_cast<float2*>(smem + STAT + r * 8);
                    int bid = *reinterpret_cast<int*>(smem + SBID + r * 4);
                    const float* gp = d_GAMMA + (size_t)bid * H_DIM;
                    const float* bp = d_BETA  + (size_t)bid * H_DIM;
#pragma unroll
                    for (int j = 0; j < 8; j++) {
                        int c = n0 + j * 8 + lq * 2;
                        float2 g2 = *reinterpret_cast<const float2*>(gp + c);
                        float2 be = *reinterpret_cast<const float2*>(bp + c);
                        float y0 = fmaxf(fmaf((acc[mi][j][half * 2 + 0] - st.x) * st.y, g2.x, be.x), 0.f);
                        float y1 = fmaxf(fmaf((acc[mi][j][half * 2 + 1] - st.x) * st.y, g2.y, be.y), 0.f);
                        sts_single2(smem, r, c, y0, y1);
                    }
                }
        }

        // ================= GEMM2 + relu + b2 =================
        run_gemm<true>(sb, flatbase + 8, total, acc, m0, n0, lane, tid);
        __syncthreads();   // all warps done reading A before overwrite
        {
#pragma unroll
            for (int mi = 0; mi < 2; mi++)
#pragma unroll
                for (int half = 0; half < 2; half++) {
                    int r = m0 + mi * 16 + half * 8 + lgrp;
#pragma unroll
                    for (int j = 0; j < 8; j++) {
                        int c = n0 + j * 8 + lq * 2;
                        float2 bb = *reinterpret_cast<const float2*>(b2 + c);
                        float y0 = fmaxf(acc[mi][j][half * 2 + 0] + bb.x, 0.f);
                        float y1 = fmaxf(acc[mi][j][half * 2 + 1] + bb.y, 0.f);
                        sts_single2(smem, r, c, y0, y1);
                    }
                }
        }

        // ================= GEMM3 (two 256-col halves) + b3 -> out =====
#pragma unroll 1
        for (int hf = 0; hf < 2; hf++) {
            if (hf == 0) run_gemm<true >(sb, flatbase + 16, total, acc, m0, n0, lane, tid);
            else         run_gemm<false>(sb, flatbase + 24, total, acc, m0, n0, lane, tid);
#pragma unroll
            for (int mi = 0; mi < 2; mi++)
#pragma unroll
                for (int half = 0; half < 2; half++) {
                    int r = m0 + mi * 16 + half * 8 + lgrp;
                    int row = row0 + r;
                    if (row < N) {
                        float* op = out + (size_t)row * OUT_DIM + hf * 256;
#pragma unroll
                        for (int j = 0; j < 8; j++) {
                            int c = n0 + j * 8 + lq * 2;
                            float2 bb = *reinterpret_cast<const float2*>(b3 + hf * 256 + c);
                            float2 o2;
                            o2.x = acc[mi][j][half * 2 + 0] + bb.x;
                            o2.y = acc[mi][j][half * 2 + 1] + bb.y;
                            *reinterpret_cast<float2*>(op + c) = o2;
                        }
                    }
                }
        }

        flatbase += 32;
    }
}

// ---------------------------------------------------------------------------
extern "C" void kernel_launch(void* const* d_in, const int* in_sizes, int n_in,
                              void* d_out, int out_size) {
    const float* x         = (const float*)d_in[0];
    const float* cond      = (const float*)d_in[1];
    const int*   batch_ids = (const int*)  d_in[2];
    const float* v_cond    = (const float*)d_in[3];
    const float* g_cond    = (const float*)d_in[4];
    const float* b_cond    = (const float*)d_in[5];
    const float* v1        = (const float*)d_in[6];
    const float* g1        = (const float*)d_in[7];
    const float* v2        = (const float*)d_in[8];
    const float* g2        = (const float*)d_in[9];
    const float* b2        = (const float*)d_in[10];
    const float* v3        = (const float*)d_in[11];
    const float* g3        = (const float*)d_in[12];
    const float* b3        = (const float*)d_in[13];
    float* out = (float*)d_out;

    int N = in_sizes[0] / K_DIM;
    int ntiles = (N + TILE_M - 1) / TILE_M;

    wn_all<<<1536, 256>>>(v_cond, g_cond, v1, g1, v2, g2, v3, g3);
    film_kernel<<<G_DIM, 256>>>(cond, b_cond);

    int dev = 0, nsm = 148;
    cudaGetDevice(&dev);
    cudaDeviceGetAttribute(&nsm, cudaDevAttrMultiProcessorCount, dev);
    int grid = 2 * nsm;
    if (grid > ntiles) grid = ntiles;

    cudaFuncSetAttribute(fused_mma, cudaFuncAttributeMaxDynamicSharedMemorySize, SMEM_TOTAL);
    fused_mma<<<grid, NTH, SMEM_TOTAL>>>(x, batch_ids, b2, b3, out, N, ntiles);
}

// round 15
// speedup vs baseline: 5.5414x; 1.0961x over previous
#include <cuda_runtime.h>
#include <cuda_fp16.h>
#include <math.h>
#include <stdint.h>

#define K_DIM 256
#define H_DIM 256
#define OUT_DIM 512
#define G_DIM 256
#define TILE_M 64
#define NTH 256

// ---- smem layout (bytes) ----
#define ASTR_B 528            // 264 fp16 per A row
#define A_HI 0                // 64 x 528 = 33792
#define PART 33792            // 64 rows x 4 warps x float2 = 2048
#define STAT 35840            // 64 x float2 = 512
#define SBID 36352            // 64 x int = 256
#define SMEM_TOTAL 36864

// ---------------- global scratch ----------------
__device__ float d_Wc[OUT_DIM * K_DIM];
__device__ float d_GAMMA[G_DIM * H_DIM];
__device__ float d_BETA[G_DIM * H_DIM];
// weight images in per-lane MMA-B-fragment order:
// per 256-row pass: offset(t16,G,lane) = ((t16*16+G)*32+lane)*16 bytes,
// 16B per lane = {b0_n8sub0, b1_n8sub0, b0_n8sub1, b1_n8sub1}
__device__ __align__(128) uint8_t d_W1f[131072];
__device__ __align__(128) uint8_t d_W2f[131072];
__device__ __align__(128) uint8_t d_W3f[262144];

// ---------------- asm helpers ----------------
__device__ __forceinline__ uint32_t smem_u32(const void* p) {
    uint32_t a;
    asm("{ .reg .u64 t; cvta.to.shared.u64 t, %1; cvt.u32.u64 %0, t; }" : "=r"(a) : "l"(p));
    return a;
}
__device__ __forceinline__ void ldsm4(uint32_t (&r)[4], uint32_t a) {
    asm volatile("ldmatrix.sync.aligned.m8n8.x4.shared.b16 {%0,%1,%2,%3}, [%4];"
                 : "=r"(r[0]), "=r"(r[1]), "=r"(r[2]), "=r"(r[3]) : "r"(a));
}
__device__ __forceinline__ void mma16816(float* c, const uint32_t* a, uint32_t b0, uint32_t b1) {
    asm volatile("mma.sync.aligned.m16n8k16.row.col.f32.f16.f16.f32 "
                 "{%0,%1,%2,%3}, {%4,%5,%6,%7}, {%8,%9}, {%0,%1,%2,%3};"
                 : "+f"(c[0]), "+f"(c[1]), "+f"(c[2]), "+f"(c[3])
                 : "r"(a[0]), "r"(a[1]), "r"(a[2]), "r"(a[3]), "r"(b0), "r"(b1));
}

// ---------------------------------------------------------------------------
// prep: all four weight norms in one launch; W1/2/3 stored in fragment order
// blocks [0,512): Wc fp32; [512,768): W1; [768,1024): W2; [1024,1536): W3
// ---------------------------------------------------------------------------
__global__ void wn_all(const float* __restrict__ v_cond, const float* __restrict__ g_cond,
                       const float* __restrict__ v1, const float* __restrict__ g1,
                       const float* __restrict__ v2, const float* __restrict__ g2,
                       const float* __restrict__ v3, const float* __restrict__ g3) {
    int b = blockIdx.x, t = threadIdx.x;
    const float *v, *g;
    int which, r;
    if (b < 512)       { which = 0; r = b;        v = v_cond; g = g_cond; }
    else if (b < 768)  { which = 1; r = b - 512;  v = v1;     g = g1; }
    else if (b < 1024) { which = 2; r = b - 768;  v = v2;     g = g2; }
    else               { which = 3; r = b - 1024; v = v3;     g = g3; }

    float x = v[r * K_DIM + t];
    float ss = x * x;
#pragma unroll
    for (int o = 16; o; o >>= 1) ss += __shfl_xor_sync(0xffffffffu, ss, o);
    __shared__ float red[8];
    __shared__ float s_scale;
    if ((t & 31) == 0) red[t >> 5] = ss;
    __syncthreads();
    if (t == 0) {
        float tot = 0.f;
#pragma unroll
        for (int i = 0; i < 8; i++) tot += red[i];
        s_scale = g[r] / sqrtf(tot);
    }
    __syncthreads();
    float wv = x * s_scale;
    if (which == 0) { d_Wc[r * K_DIM + t] = wv; return; }
    uint8_t* img = (which == 1) ? d_W1f : (which == 2) ? d_W2f : d_W3f;
    int p = r >> 8, n = r & 255;
    int k = t;
    // B-fragment placement for mma.m16n8k16 row.col
    int t16 = k >> 4, G = n >> 4;
    int s_n = (n >> 3) & 1, n8v = n & 7;
    int half = (k >> 3) & 1, k8 = k & 7;
    int lanei = n8v * 4 + (k8 >> 1);
    int regi = s_n * 2 + half;
    size_t off = ((size_t)((t16 * 16 + G) * 32 + lanei) * 16) + regi * 4 + (k8 & 1) * 2;
    *reinterpret_cast<__half*>(img + (size_t)p * 131072 + off) = __float2half(wv);
}

__global__ void film_kernel(const float* __restrict__ cond, const float* __restrict__ b_cond) {
    __shared__ float cs[K_DIM];
    int g = blockIdx.x, t = threadIdx.x;
    cs[t] = cond[g * K_DIM + t];
    __syncthreads();
    const float* w0 = d_Wc + (size_t)t * K_DIM;
    const float* w1 = d_Wc + (size_t)(t + 256) * K_DIM;
    float a0 = 0.f, a1 = 0.f;
#pragma unroll 8
    for (int k = 0; k < K_DIM; k++) {
        float c = cs[k];
        a0 = fmaf(c, w0[k], a0);
        a1 = fmaf(c, w1[k], a1);
    }
    d_GAMMA[g * H_DIM + t] = a0 + b_cond[t] + 1.0f;
    d_BETA[g * H_DIM + t]  = a1 + b_cond[t + 256];
}

// ---------------------------------------------------------------------------
// one full GEMM pass: acc[64x256] += A(smem fp16) @ W(L2, fragment-order)^T
// ---------------------------------------------------------------------------
__device__ __forceinline__ void run_pass(uint32_t sb, const uint8_t* __restrict__ wimg,
                                         float (&acc)[2][8][4],
                                         int m0, int warp_n, int lane) {
#pragma unroll
    for (int i = 0; i < 2; i++)
#pragma unroll
        for (int j = 0; j < 8; j++)
#pragma unroll
            for (int qq = 0; qq < 4; qq++) acc[i][j][qq] = 0.f;

    const uint32_t abase = sb + A_HI + (m0 + (lane & 15)) * ASTR_B + (lane >> 4) * 16;
    const uint4* __restrict__ wbase =
        reinterpret_cast<const uint4*>(wimg) + (size_t)(warp_n * 4) * 32 + lane;

#pragma unroll
    for (int t = 0; t < 16; t++) {
        uint32_t ah0[4], ah1[4];
        uint32_t aoff = abase + t * 32;           // t16 * 16 halves * 2B
        ldsm4(ah0, aoff);
        ldsm4(ah1, aoff + 16 * ASTR_B);
        uint4 wv[4];
#pragma unroll
        for (int g = 0; g < 4; g++)
            wv[g] = wbase[t * 512 + g * 32];      // ((t*16 + warp_n*4+g)*32 + lane)
#pragma unroll
        for (int g = 0; g < 4; g++) {
            mma16816(acc[0][2 * g + 0], ah0, wv[g].x, wv[g].y);
            mma16816(acc[0][2 * g + 1], ah0, wv[g].z, wv[g].w);
            mma16816(acc[1][2 * g + 0], ah1, wv[g].x, wv[g].y);
            mma16816(acc[1][2 * g + 1], ah1, wv[g].z, wv[g].w);
        }
    }
}

// single-limb fp16 store into A at (row, k pair)
__device__ __forceinline__ void sts_single2(char* smem, int row, int k, float y0, float y1) {
    uint32_t off = row * ASTR_B + k * 2;
    *reinterpret_cast<__half2*>(smem + A_HI + off) =
        __halves2half2(__float2half_rn(y0), __float2half_rn(y1));
}

// ---------------------------------------------------------------------------
__global__ void __launch_bounds__(NTH, 2)
fused_mma(const float* __restrict__ x,
          const int* __restrict__ bids,
          const float* __restrict__ b2,
          const float* __restrict__ b3,
          float* __restrict__ out, int N) {
    extern __shared__ __align__(128) char smem[];
    const uint32_t sb = smem_u32(smem);
    const int tid = threadIdx.x;
    const int lane = tid & 31, w = tid >> 5;
    const int warp_m = w >> 2, warp_n = w & 3;    // 2 x 4 warps
    const int m0 = warp_m * 32, n0 = warp_n * 64;
    const int lgrp = lane >> 2, lq = lane & 3;
    const int row0 = blockIdx.x * TILE_M;

    // ---- build A (single fp16) from x tile [64 x 256] ----
#pragma unroll 4
    for (int i = 0; i < 16; i++) {
        int idx = tid + NTH * i;
        int m = idx >> 6, c4 = idx & 63;
        int row = row0 + m;
        float4 v = (row < N) ? reinterpret_cast<const float4*>(x)[(size_t)row * 64 + c4]
                             : make_float4(0.f, 0.f, 0.f, 0.f);
        sts_single2(smem, m, c4 * 4 + 0, v.x, v.y);
        sts_single2(smem, m, c4 * 4 + 2, v.z, v.w);
    }
    __syncthreads();

    float acc[2][8][4];

    // ================= GEMM1 + layernorm/FiLM/relu =================
    run_pass(sb, d_W1f, acc, m0, warp_n, lane);
    {
#pragma unroll
        for (int mi = 0; mi < 2; mi++)
#pragma unroll
            for (int half = 0; half < 2; half++) {
                float s = 0.f, ss = 0.f;
#pragma unroll
                for (int j = 0; j < 8; j++) {
                    float v0 = acc[mi][j][half * 2 + 0];
                    float v1 = acc[mi][j][half * 2 + 1];
                    s += v0 + v1;
                    ss = fmaf(v0, v0, fmaf(v1, v1, ss));
                }
                s  += __shfl_xor_sync(0xffffffffu, s, 1);
                s  += __shfl_xor_sync(0xffffffffu, s, 2);
                ss += __shfl_xor_sync(0xffffffffu, ss, 1);
                ss += __shfl_xor_sync(0xffffffffu, ss, 2);
                if (lq == 0) {
                    int r = m0 + mi * 16 + half * 8 + lgrp;
                    *reinterpret_cast<float2*>(smem + PART + (r * 4 + warp_n) * 8) =
                        make_float2(s, ss);
                }
            }
        __syncthreads();   // all warps done GEMM1 + partials published
        if (tid < TILE_M) {
            float s = 0.f, ss = 0.f;
#pragma unroll
            for (int qq = 0; qq < 4; qq++) {
                float2 p = *reinterpret_cast<float2*>(smem + PART + (tid * 4 + qq) * 8);
                s += p.x;
                ss += p.y;
            }
            float mu = s * (1.f / 256.f);
            float var = ss * (1.f / 256.f) - mu * mu;
            float rstd = rsqrtf(var + 1e-5f);
            *reinterpret_cast<float2*>(smem + STAT + tid * 8) = make_float2(mu, rstd);
            int row = row0 + tid;
            *reinterpret_cast<int*>(smem + SBID + tid * 4) = (row < N) ? bids[row] : 0;
        }
        __syncthreads();
#pragma unroll
        for (int mi = 0; mi < 2; mi++)
#pragma unroll
            for (int half = 0; half < 2; half++) {
                int r = m0 + mi * 16 + half * 8 + lgrp;
                float2 st = *reinterpret_cast<float2*>(smem + STAT + r * 8);
                int bid = *reinterpret_cast<int*>(smem + SBID + r * 4);
                const float* gp = d_GAMMA + (size_t)bid * H_DIM;
                const float* bp = d_BETA  + (size_t)bid * H_DIM;
#pragma unroll
                for (int j = 0; j < 8; j++) {
                    int c = n0 + j * 8 + lq * 2;
                    float2 g2 = *reinterpret_cast<const float2*>(gp + c);
                    float2 be = *reinterpret_cast<const float2*>(bp + c);
                    float y0 = fmaxf(fmaf((acc[mi][j][half * 2 + 0] - st.x) * st.y, g2.x, be.x), 0.f);
                    float y1 = fmaxf(fmaf((acc[mi][j][half * 2 + 1] - st.x) * st.y, g2.y, be.y), 0.f);
                    sts_single2(smem, r, c, y0, y1);
                }
            }
    }
    __syncthreads();   // A rewrite complete before GEMM2 reads

    // ================= GEMM2 + relu + b2 =================
    run_pass(sb, d_W2f, acc, m0, warp_n, lane);
    __syncthreads();   // all warps done reading A before overwrite
    {
#pragma unroll
        for (int mi = 0; mi < 2; mi++)
#pragma unroll
            for (int half = 0; half < 2; half++) {
                int r = m0 + mi * 16 + half * 8 + lgrp;
#pragma unroll
                for (int j = 0; j < 8; j++) {
                    int c = n0 + j * 8 + lq * 2;
                    float2 bb = *reinterpret_cast<const float2*>(b2 + c);
                    float y0 = fmaxf(acc[mi][j][half * 2 + 0] + bb.x, 0.f);
                    float y1 = fmaxf(acc[mi][j][half * 2 + 1] + bb.y, 0.f);
                    sts_single2(smem, r, c, y0, y1);
                }
            }
    }
    __syncthreads();   // A rewrite complete before GEMM3 reads

    // ================= GEMM3 (two 256-col halves) + b3 -> out =====
#pragma unroll 1
    for (int hf = 0; hf < 2; hf++) {
        run_pass(sb, d_W3f + (size_t)hf * 131072, acc, m0, warp_n, lane);
#pragma unroll
        for (int mi = 0; mi < 2; mi++)
#pragma unroll
            for (int half = 0; half < 2; half++) {
                int r = m0 + mi * 16 + half * 8 + lgrp;
                int row = row0 + r;
                if (row < N) {
                    float* op = out + (size_t)row * OUT_DIM + hf * 256;
#pragma unroll
                    for (int j = 0; j < 8; j++) {
                        int c = n0 + j * 8 + lq * 2;
                        float2 bb = *reinterpret_cast<const float2*>(b3 + hf * 256 + c);
                        float2 o2;
                        o2.x = acc[mi][j][half * 2 + 0] + bb.x;
                        o2.y = acc[mi][j][half * 2 + 1] + bb.y;
                        *reinterpret_cast<float2*>(op + c) = o2;
                    }
                }
            }
    }
}

// ---------------------------------------------------------------------------
extern "C" void kernel_launch(void* const* d_in, const int* in_sizes, int n_in,
                              void* d_out, int out_size) {
    const float* x         = (const float*)d_in[0];
    const float* cond      = (const float*)d_in[1];
    const int*   batch_ids = (const int*)  d_in[2];
    const float* v_cond    = (const float*)d_in[3];
    const float* g_cond    = (const float*)d_in[4];
    const float* b_cond    = (const float*)d_in[5];
    const float* v1        = (const float*)d_in[6];
    const float* g1        = (const float*)d_in[7];
    const float* v2        = (const float*)d_in[8];
    const float* g2        = (const float*)d_in[9];
    const float* b2        = (const float*)d_in[10];
    const float* v3        = (const float*)d_in[11];
    const float* g3        = (const float*)d_in[12];
    const float* b3        = (const float*)d_in[13];
    float* out = (float*)d_out;

    int N = in_sizes[0] / K_DIM;
    int ntiles = (N + TILE_M - 1) / TILE_M;

    wn_all<<<1536, 256>>>(v_cond, g_cond, v1, g1, v2, g2, v3, g3);
    film_kernel<<<G_DIM, 256>>>(cond, b_cond);

    cudaFuncSetAttribute(fused_mma, cudaFuncAttributeMaxDynamicSharedMemorySize, SMEM_TOTAL);
    fused_mma<<<ntiles, NTH, SMEM_TOTAL>>>(x, batch_ids, b2, b3, out, N);
}

// round 16
// speedup vs baseline: 5.6743x; 1.0240x over previous
#include <cuda_runtime.h>
#include <cuda_fp16.h>
#include <math.h>
#include <stdint.h>

#define K_DIM 256
#define H_DIM 256
#define OUT_DIM 512
#define G_DIM 256
#define TILE_M 64
#define NTH 256

// ---- smem layout (bytes) ----
#define ASTR_B 528            // 264 fp16 per A row
#define A_HI 0                // 64 x 528 = 33792
#define PART 33792            // 64 rows x 4 warps x float2 = 2048
#define STAT 35840            // 64 x float2 = 512
#define SBID 36352            // 64 x int = 256
#define SMEM_TOTAL 36864

// ---------------- global scratch ----------------
__device__ float d_Wc[OUT_DIM * K_DIM];
__device__ float d_GAMMA[G_DIM * H_DIM];
__device__ float d_BETA[G_DIM * H_DIM];
// weight images in per-lane MMA-B-fragment order:
// per 256-row pass: offset(t16,G,lane) = ((t16*16+G)*32+lane)*16 bytes
__device__ __align__(128) uint8_t d_W1f[131072];
__device__ __align__(128) uint8_t d_W2f[131072];
__device__ __align__(128) uint8_t d_W3f[262144];

// ---------------- asm helpers ----------------
__device__ __forceinline__ uint32_t smem_u32(const void* p) {
    uint32_t a;
    asm("{ .reg .u64 t; cvta.to.shared.u64 t, %1; cvt.u32.u64 %0, t; }" : "=r"(a) : "l"(p));
    return a;
}
__device__ __forceinline__ void ldsm4(uint32_t (&r)[4], uint32_t a) {
    asm volatile("ldmatrix.sync.aligned.m8n8.x4.shared.b16 {%0,%1,%2,%3}, [%4];"
                 : "=r"(r[0]), "=r"(r[1]), "=r"(r[2]), "=r"(r[3]) : "r"(a));
}
__device__ __forceinline__ void mma16816(float* c, const uint32_t* a, uint32_t b0, uint32_t b1) {
    asm volatile("mma.sync.aligned.m16n8k16.row.col.f32.f16.f16.f32 "
                 "{%0,%1,%2,%3}, {%4,%5,%6,%7}, {%8,%9}, {%0,%1,%2,%3};"
                 : "+f"(c[0]), "+f"(c[1]), "+f"(c[2]), "+f"(c[3])
                 : "r"(a[0]), "r"(a[1]), "r"(a[2]), "r"(a[3]), "r"(b0), "r"(b1));
}

// ---------------------------------------------------------------------------
// prep: all four weight norms in one launch; W1/2/3 stored in fragment order
// ---------------------------------------------------------------------------
__global__ void wn_all(const float* __restrict__ v_cond, const float* __restrict__ g_cond,
                       const float* __restrict__ v1, const float* __restrict__ g1,
                       const float* __restrict__ v2, const float* __restrict__ g2,
                       const float* __restrict__ v3, const float* __restrict__ g3) {
    int b = blockIdx.x, t = threadIdx.x;
    const float *v, *g;
    int which, r;
    if (b < 512)       { which = 0; r = b;        v = v_cond; g = g_cond; }
    else if (b < 768)  { which = 1; r = b - 512;  v = v1;     g = g1; }
    else if (b < 1024) { which = 2; r = b - 768;  v = v2;     g = g2; }
    else               { which = 3; r = b - 1024; v = v3;     g = g3; }

    float x = v[r * K_DIM + t];
    float ss = x * x;
#pragma unroll
    for (int o = 16; o; o >>= 1) ss += __shfl_xor_sync(0xffffffffu, ss, o);
    __shared__ float red[8];
    __shared__ float s_scale;
    if ((t & 31) == 0) red[t >> 5] = ss;
    __syncthreads();
    if (t == 0) {
        float tot = 0.f;
#pragma unroll
        for (int i = 0; i < 8; i++) tot += red[i];
        s_scale = g[r] / sqrtf(tot);
    }
    __syncthreads();
    float wv = x * s_scale;
    if (which == 0) { d_Wc[r * K_DIM + t] = wv; return; }
    uint8_t* img = (which == 1) ? d_W1f : (which == 2) ? d_W2f : d_W3f;
    int p = r >> 8, n = r & 255;
    int k = t;
    int t16 = k >> 4, G = n >> 4;
    int s_n = (n >> 3) & 1, n8v = n & 7;
    int half = (k >> 3) & 1, k8 = k & 7;
    int lanei = n8v * 4 + (k8 >> 1);
    int regi = s_n * 2 + half;
    size_t off = ((size_t)((t16 * 16 + G) * 32 + lanei) * 16) + regi * 4 + (k8 & 1) * 2;
    *reinterpret_cast<__half*>(img + (size_t)p * 131072 + off) = __float2half(wv);
}

__global__ void film_kernel(const float* __restrict__ cond, const float* __restrict__ b_cond) {
    __shared__ float cs[K_DIM];
    int g = blockIdx.x, t = threadIdx.x;
    cs[t] = cond[g * K_DIM + t];
    __syncthreads();
    const float* w0 = d_Wc + (size_t)t * K_DIM;
    const float* w1 = d_Wc + (size_t)(t + 256) * K_DIM;
    float a0 = 0.f, a1 = 0.f;
#pragma unroll 8
    for (int k = 0; k < K_DIM; k++) {
        float c = cs[k];
        a0 = fmaf(c, w0[k], a0);
        a1 = fmaf(c, w1[k], a1);
    }
    d_GAMMA[g * H_DIM + t] = a0 + b_cond[t] + 1.0f;
    d_BETA[g * H_DIM + t]  = a1 + b_cond[t + 256];
}

// ---------------------------------------------------------------------------
// one full GEMM pass with hoisted t0 loads + register double-buffered W.
// SYNC: emit the A-availability __syncthreads AFTER issuing t0 W loads.
// ---------------------------------------------------------------------------
template <bool SYNC>
__device__ __forceinline__ void run_pass(uint32_t sb, const uint8_t* __restrict__ wimg,
                                         float (&acc)[2][8][4],
                                         int m0, int warp_n, int lane) {
#pragma unroll
    for (int i = 0; i < 2; i++)
#pragma unroll
        for (int j = 0; j < 8; j++)
#pragma unroll
            for (int qq = 0; qq < 4; qq++) acc[i][j][qq] = 0.f;

    const uint32_t abase = sb + A_HI + (m0 + (lane & 15)) * ASTR_B + (lane >> 4) * 16;
    const uint4* __restrict__ wbase =
        reinterpret_cast<const uint4*>(wimg) + (size_t)(warp_n * 4) * 32 + lane;

    uint4 wv[4];
#pragma unroll
    for (int g = 0; g < 4; g++) wv[g] = wbase[g * 32];   // t=0, issued pre-barrier
    if (SYNC) __syncthreads();                            // A tile ready

#pragma unroll
    for (int t = 0; t < 16; t++) {
        uint32_t ah0[4], ah1[4];
        uint32_t aoff = abase + t * 32;
        ldsm4(ah0, aoff);
        ldsm4(ah1, aoff + 16 * ASTR_B);
        uint4 wn[4];
        if (t < 15) {
#pragma unroll
            for (int g = 0; g < 4; g++) wn[g] = wbase[(t + 1) * 512 + g * 32];
        }
#pragma unroll
        for (int g = 0; g < 4; g++) {
            mma16816(acc[0][2 * g + 0], ah0, wv[g].x, wv[g].y);
            mma16816(acc[0][2 * g + 1], ah0, wv[g].z, wv[g].w);
            mma16816(acc[1][2 * g + 0], ah1, wv[g].x, wv[g].y);
            mma16816(acc[1][2 * g + 1], ah1, wv[g].z, wv[g].w);
        }
        if (t < 15) {
#pragma unroll
            for (int g = 0; g < 4; g++) wv[g] = wn[g];
        }
    }
}

// single-limb fp16 store into A at (row, k pair)
__device__ __forceinline__ void sts_single2(char* smem, int row, int k, float y0, float y1) {
    uint32_t off = row * ASTR_B + k * 2;
    *reinterpret_cast<__half2*>(smem + A_HI + off) =
        __halves2half2(__float2half_rn(y0), __float2half_rn(y1));
}

// ---------------------------------------------------------------------------
__global__ void __launch_bounds__(NTH, 2)
fused_mma(const float* __restrict__ x,
          const int* __restrict__ bids,
          const float* __restrict__ b2,
          const float* __restrict__ b3,
          float* __restrict__ out, int N) {
    extern __shared__ __align__(128) char smem[];
    const uint32_t sb = smem_u32(smem);
    const int tid = threadIdx.x;
    const int lane = tid & 31, w = tid >> 5;
    const int warp_m = w >> 2, warp_n = w & 3;    // 2 x 4 warps
    const int m0 = warp_m * 32, n0 = warp_n * 64;
    const int lgrp = lane >> 2, lq = lane & 3;
    const int row0 = blockIdx.x * TILE_M;

    // ---- prefetch batch ids (independent of GEMM1) ----
    if (tid < TILE_M) {
        int row = row0 + tid;
        *reinterpret_cast<int*>(smem + SBID + tid * 4) = (row < N) ? bids[row] : 0;
    }

    // ---- build A (single fp16) from x tile [64 x 256] ----
#pragma unroll 4
    for (int i = 0; i < 16; i++) {
        int idx = tid + NTH * i;
        int m = idx >> 6, c4 = idx & 63;
        int row = row0 + m;
        float4 v = (row < N) ? reinterpret_cast<const float4*>(x)[(size_t)row * 64 + c4]
                             : make_float4(0.f, 0.f, 0.f, 0.f);
        sts_single2(smem, m, c4 * 4 + 0, v.x, v.y);
        sts_single2(smem, m, c4 * 4 + 2, v.z, v.w);
    }

    float acc[2][8][4];

    // ================= GEMM1 + layernorm/FiLM/relu =================
    run_pass<true>(sb, d_W1f, acc, m0, warp_n, lane);
    {
#pragma unroll
        for (int mi = 0; mi < 2; mi++)
#pragma unroll
            for (int half = 0; half < 2; half++) {
                float s = 0.f, ss = 0.f;
#pragma unroll
                for (int j = 0; j < 8; j++) {
                    float v0 = acc[mi][j][half * 2 + 0];
                    float v1 = acc[mi][j][half * 2 + 1];
                    s += v0 + v1;
                    ss = fmaf(v0, v0, fmaf(v1, v1, ss));
                }
                s  += __shfl_xor_sync(0xffffffffu, s, 1);
                s  += __shfl_xor_sync(0xffffffffu, s, 2);
                ss += __shfl_xor_sync(0xffffffffu, ss, 1);
                ss += __shfl_xor_sync(0xffffffffu, ss, 2);
                if (lq == 0) {
                    int r = m0 + mi * 16 + half * 8 + lgrp;
                    *reinterpret_cast<float2*>(smem + PART + (r * 4 + warp_n) * 8) =
                        make_float2(s, ss);
                }
            }
        __syncthreads();   // all warps done GEMM1 + partials published
        if (tid < TILE_M) {
            float s = 0.f, ss = 0.f;
#pragma unroll
            for (int qq = 0; qq < 4; qq++) {
                float2 p = *reinterpret_cast<float2*>(smem + PART + (tid * 4 + qq) * 8);
                s += p.x;
                ss += p.y;
            }
            float mu = s * (1.f / 256.f);
            float var = ss * (1.f / 256.f) - mu * mu;
            float rstd = rsqrtf(var + 1e-5f);
            *reinterpret_cast<float2*>(smem + STAT + tid * 8) = make_float2(mu, rstd);
        }
        __syncthreads();
#pragma unroll
        for (int mi = 0; mi < 2; mi++)
#pragma unroll
            for (int half = 0; half < 2; half++) {
                int r = m0 + mi * 16 + half * 8 + lgrp;
                float2 st = *reinterpret_cast<float2*>(smem + STAT + r * 8);
                int bid = *reinterpret_cast<int*>(smem + SBID + r * 4);
                const float* gp = d_GAMMA + (size_t)bid * H_DIM;
                const float* bp = d_BETA  + (size_t)bid * H_DIM;
#pragma unroll
                for (int j = 0; j < 8; j++) {
                    int c = n0 + j * 8 + lq * 2;
                    float2 g2 = *reinterpret_cast<const float2*>(gp + c);
                    float2 be = *reinterpret_cast<const float2*>(bp + c);
                    float y0 = fmaxf(fmaf((acc[mi][j][half * 2 + 0] - st.x) * st.y, g2.x, be.x), 0.f);
                    float y1 = fmaxf(fmaf((acc[mi][j][half * 2 + 1] - st.x) * st.y, g2.y, be.y), 0.f);
                    sts_single2(smem, r, c, y0, y1);
                }
            }
    }

    // ================= GEMM2 + relu + b2 =================
    run_pass<true>(sb, d_W2f, acc, m0, warp_n, lane);
    __syncthreads();   // all warps done reading A before overwrite
    {
#pragma unroll
        for (int mi = 0; mi < 2; mi++)
#pragma unroll
            for (int half = 0; half < 2; half++) {
                int r = m0 + mi * 16 + half * 8 + lgrp;
#pragma unroll
                for (int j = 0; j < 8; j++) {
                    int c = n0 + j * 8 + lq * 2;
                    float2 bb = *reinterpret_cast<const float2*>(b2 + c);
                    float y0 = fmaxf(acc[mi][j][half * 2 + 0] + bb.x, 0.f);
                    float y1 = fmaxf(acc[mi][j][half * 2 + 1] + bb.y, 0.f);
                    sts_single2(smem, r, c, y0, y1);
                }
            }
    }

    // ================= GEMM3 (two 256-col halves) + b3 -> out =====
#pragma unroll 1
    for (int hf = 0; hf < 2; hf++) {
        if (hf == 0) run_pass<true >(sb, d_W3f, acc, m0, warp_n, lane);
        else         run_pass<false>(sb, d_W3f + 131072, acc, m0, warp_n, lane);
#pragma unroll
        for (int mi = 0; mi < 2; mi++)
#pragma unroll
            for (int half = 0; half < 2; half++) {
                int r = m0 + mi * 16 + half * 8 + lgrp;
                int row = row0 + r;
                if (row < N) {
                    float* op = out + (size_t)row * OUT_DIM + hf * 256;
#pragma unroll
                    for (int j = 0; j < 8; j++) {
                        int c = n0 + j * 8 + lq * 2;
                        float2 bb = *reinterpret_cast<const float2*>(b3 + hf * 256 + c);
                        float2 o2;
                        o2.x = acc[mi][j][half * 2 + 0] + bb.x;
                        o2.y = acc[mi][j][half * 2 + 1] + bb.y;
                        *reinterpret_cast<float2*>(op + c) = o2;
                    }
                }
            }
    }
}

// ---------------------------------------------------------------------------
extern "C" void kernel_launch(void* const* d_in, const int* in_sizes, int n_in,
                              void* d_out, int out_size) {
    const float* x         = (const float*)d_in[0];
    const float* cond      = (const float*)d_in[1];
    const int*   batch_ids = (const int*)  d_in[2];
    const float* v_cond    = (const float*)d_in[3];
    const float* g_cond    = (const float*)d_in[4];
    const float* b_cond    = (const float*)d_in[5];
    const float* v1        = (const float*)d_in[6];
    const float* g1        = (const float*)d_in[7];
    const float* v2        = (const float*)d_in[8];
    const float* g2        = (const float*)d_in[9];
    const float* b2        = (const float*)d_in[10];
    const float* v3        = (const float*)d_in[11];
    const float* g3        = (const float*)d_in[12];
    const float* b3        = (const float*)d_in[13];
    float* out = (float*)d_out;

    int N = in_sizes[0] / K_DIM;
    int ntiles = (N + TILE_M - 1) / TILE_M;

    wn_all<<<1536, 256>>>(v_cond, g_cond, v1, g1, v2, g2, v3, g3);
    film_kernel<<<G_DIM, 256>>>(cond, b_cond);

    cudaFuncSetAttribute(fused_mma, cudaFuncAttributeMaxDynamicSharedMemorySize, SMEM_TOTAL);
    fused_mma<<<ntiles, NTH, SMEM_TOTAL>>>(x, batch_ids, b2, b3, out, N);
}